// round 7
// baseline (speedup 1.0000x reference)
#include <cuda_runtime.h>
#include <cstdint>
#include <cstddef>

#define B_   4
#define NP_  512
#define NC_  256
#define E_   128
#define C_   32
#define Q_   (NP_*NC_)          // 131072
#define CQ_  (C_*Q_)            // 4194304 per batch
#define NB_  20

typedef unsigned long long ull;

// ---------------- f32x2 packed helpers ------------------------------------
#define FMA2(d, a, b) asm("fma.rn.f32x2 %0, %1, %2, %0;" : "+l"(d) : "l"(a), "l"(b))
__device__ __forceinline__ ull pack2(float x, float y) {
    ull r; asm("mov.b64 %0, {%1, %2};" : "=l"(r) : "f"(x), "f"(y)); return r;
}
__device__ __forceinline__ void unpack2(float& x, float& y, ull v) {
    asm("mov.b64 {%0, %1}, %2;" : "=f"(x), "=f"(y) : "l"(v));
}

// ---------------- scratch (device globals; no allocation) ----------------
__device__ float g_disb[(size_t)B_*NP_*NC_*C_];   // natural [b][np][nc][cc] flat
__device__ float g_lig [(size_t)B_*C_*NC_*E_];    // [b][cc][nc][e]
__device__ float g_part[(size_t)8*1024*128];      // split-K partials for k_out
__device__ float g_acc [8];                       // [0..3]=energy, [4..7]=prmsd
__device__ int   g_mtype;                         // 0=u8, 1=i32, 2=f32

// ---------------- K-1: detect z_mask dtype --------------------------------
__global__ void k_detect(const unsigned int* __restrict__ m)
{
    if (threadIdx.x == 0) {
        bool alli = true, allf = true;
        for (int i = 0; i < 64; i++) {
            unsigned int v = m[i * 97];
            if (!(v == 0u || v == 1u))           alli = false;
            if (!(v == 0u || v == 0x3F800000u))  allf = false;
        }
        g_mtype = alli ? 1 : (allf ? 2 : 0);
    }
}

__device__ __forceinline__ bool mask_at(const void* zm, size_t idx, int mt)
{
    if (mt == 1) return ((const int*)zm)[idx] != 0;
    if (mt == 2) return ((const float*)zm)[idx] != 0.f;
    return ((const unsigned char*)zm)[idx] != 0;
}

// ---------------- K0: distance-bucket bias --------------------------------
__global__ void __launch_bounds__(256) k_disb(const float* __restrict__ cand,
                                              const float* __restrict__ Wd,
                                              const float* __restrict__ bd)
{
    __shared__ float sWd[NB_*32];
    __shared__ float sBd[32];
    int t = threadIdx.x;
    for (int i = t; i < NB_*32; i += 256) sWd[i] = Wd[i];
    if (t < 32) sBd[t] = bd[t];
    __syncthreads();

    int w = t >> 5, lane = t & 31;
    int s = blockIdx.x * 8 + w;              // s = (b*NP+np)*NC+nc
    float x = cand[s];

    float ev = 0.f;
    if (lane < NB_) {
        float v  = (float)(lane + 1) * (15.0f / 21.0f);
        float d  = (x - v) * (21.0f / 15.0f);
        float a  = d + 1.0f;
        float c2 = 1.0f - d;
        if (a > 0.f && c2 > 0.f)
            ev = 8.4335730689f * __expf(-__fdividef(1.f, a) - __fdividef(1.f, c2));
    }
    float acc = sBd[lane];
#pragma unroll
    for (int k = 0; k < NB_; k++) {
        float ek = __shfl_sync(0xffffffffu, ev, k);
        acc = fmaf(ek, sWd[k*32 + lane], acc);
    }
    g_disb[(size_t)s * 32 + lane] = acc;

    if (blockIdx.x == 0 && t < 8) g_acc[t] = 0.f;   // stream-ordered before k_main
}

// ---------------- K1: fused zlin GEMM + softmax + bias + mask + energy + lig
// 512 threads (16 warps), targeted 2 blocks/SM. Dynamic smem (floats):
//   [0, 8320)       U: phase1 = sWt[32][132] (4224) + sZ[16w][2r][128] (4096)
//                      lig    = sP[64][128]  (8192)
//   [8320, 25728)   sT[512][34]
//   [25728, 25856)  sWE/sWG/sWEP/sWGP (4x32)
//   [25856, 25888)  sRed[32]
// Total 25888 floats = 103552 B -> 2 CTAs/SM.
__global__ void __launch_bounds__(512, 2) k_main(const float* __restrict__ z,
                                              const void* __restrict__ zmask,
                                              const float* __restrict__ pocket,
                                              const float* __restrict__ Wlin,
                                              const float* __restrict__ blin,
                                              const float* __restrict__ We,  const float* __restrict__ be,
                                              const float* __restrict__ Wg,  const float* __restrict__ bg,
                                              const float* __restrict__ Wep, const float* __restrict__ bep,
                                              const float* __restrict__ Wgp, const float* __restrict__ bgp)
{
    extern __shared__ float smem[];
    float* sWt  = smem;                  // [32][132] transposed W_lin
    float* sZ   = smem + 4224;           // 16 warps x 2 rows x 128
    float* sP   = smem;                  // lig-phase pocket chunk (aliases sWt+sZ)
    float* sT   = smem + 8320;           // [512][34]
    float* sWE  = smem + 25728;
    float* sWG  = sWE + 32;
    float* sWEP = sWG + 32;
    float* sWGP = sWEP + 32;
    float* sRed = sWGP + 32;             // [32]

    int t    = threadIdx.x;
    int b    = blockIdx.x >> 8;
    int nc   = blockIdx.x & 255;
    int w    = t >> 5, lane = t & 31;
    int mt   = g_mtype;

    // transpose-load W_lin: sWt[cc][k] = Wlin[k][cc]
    for (int i = t; i < 32*128; i += 512) {
        int cc = i & 31, k = i >> 5;
        sWt[cc*132 + k] = Wlin[k*32 + cc];
    }
    if (t < 32) { sWE[t] = We[t]; sWG[t] = Wg[t]; sWEP[t] = Wep[t]; sWGP[t] = Wgp[t]; }
    __syncthreads();

    float bl = blin[lane];

    // ---- phase 1: z @ W_lin + b_lin (packed f32x2, 16 warps x 2 rows) ----
    {
        const size_t rstep = (size_t)16 * NC_ * E_;     // np stride of 16
        const float* zp0 = z + (((size_t)b * NP_ + w) * NC_ + nc) * E_;
        const ulonglong2* wrow = reinterpret_cast<const ulonglong2*>(sWt + lane*132);
        const ulonglong2* sZ0 = reinterpret_cast<const ulonglong2*>(sZ + (w*2 + 0)*128);
        const ulonglong2* sZ1 = reinterpret_cast<const ulonglong2*>(sZ + (w*2 + 1)*128);

        float4 cur[2], nxt[2];
        cur[0] = reinterpret_cast<const float4*>(zp0)[lane];
        cur[1] = reinterpret_cast<const float4*>(zp0 + rstep)[lane];

        for (int g = 0; g < 16; g++) {
            if (g < 15) {
                const float* zn = zp0 + (size_t)(2*g + 2) * rstep;
                nxt[0] = reinterpret_cast<const float4*>(zn)[lane];
                nxt[1] = reinterpret_cast<const float4*>(zn + rstep)[lane];
            }
            reinterpret_cast<float4*>(sZ + (w*2 + 0)*128)[lane] = cur[0];
            reinterpret_cast<float4*>(sZ + (w*2 + 1)*128)[lane] = cur[1];
            __syncwarp();

            ull accA[2] = {0ull,0ull};
            ull accB[2] = {0ull,0ull};
#pragma unroll
            for (int k4 = 0; k4 < 32; k4++) {
                ulonglong2 wv = wrow[k4];
                ulonglong2 v0 = sZ0[k4];
                ulonglong2 v1 = sZ1[k4];
                FMA2(accA[0], v0.x, wv.x);
                FMA2(accB[0], v0.y, wv.y);
                FMA2(accA[1], v1.x, wv.x);
                FMA2(accB[1], v1.y, wv.y);
            }
#pragma unroll
            for (int j = 0; j < 2; j++) {
                float ax, ay, bx, by;
                unpack2(ax, ay, accA[j]);
                unpack2(bx, by, accB[j]);
                int np = w + 16 * (2*g + j);
                sT[np*34 + lane] = (ax + bx) + (ay + by) + bl;
                cur[j] = nxt[j];
            }
            __syncwarp();
        }
    }
    __syncthreads();

    // ---- phase 2: softmax over np, + dis_bias, weird-reshape mask ----
    for (int cr = w; cr < 32; cr += 16) {
        float vv[16];
        float mx = -3.0e38f;
#pragma unroll
        for (int i = 0; i < 16; i++) { vv[i] = sT[(lane + 32*i)*34 + cr]; mx = fmaxf(mx, vv[i]); }
#pragma unroll
        for (int off = 16; off >= 1; off >>= 1) mx = fmaxf(mx, __shfl_xor_sync(0xffffffffu, mx, off));
        float sum = 0.f;
#pragma unroll
        for (int i = 0; i < 16; i++) { vv[i] = __expf(vv[i] - mx); sum += vv[i]; }
#pragma unroll
        for (int off = 16; off >= 1; off >>= 1) sum += __shfl_xor_sync(0xffffffffu, sum, off);
        float inv = 1.0f / sum;

        size_t gb = (size_t)b * CQ_ + (size_t)(cr * NC_ + nc) * NP_;
        size_t mb = (size_t)(cr & 3) * Q_ + (size_t)nc * NP_;
#pragma unroll
        for (int i = 0; i < 16; i++) {
            int np = lane + 32 * i;
            float val = fmaf(vv[i], inv, g_disb[gb + np]);
            if (mask_at(zmask, mb + np, mt)) val = 1e-9f;
            sT[np*34 + cr] = val;
        }
    }
    __syncthreads();

    // ---- phase 3: gated energy heads, accumulate per-b ----
    {
        float bE = be[0], bG = bg[0], bEp = bep[0], bGp = bgp[0];
        float se = 0.f, sp = 0.f;
        {
            int np = t;
            float ea = 0.f, ga = 0.f, e2 = 0.f, g2 = 0.f;
#pragma unroll
            for (int cc = 0; cc < 32; cc++) {
                float v = sT[np*34 + cc];
                ea = fmaf(v, sWE[cc],  ea);
                ga = fmaf(v, sWG[cc],  ga);
                e2 = fmaf(v, sWEP[cc], e2);
                g2 = fmaf(v, sWGP[cc], g2);
            }
            if (mask_at(zmask, ((size_t)b * NP_ + np) * NC_ + nc, mt)) {
                se = (ea + bE)  / (1.f + __expf(-(ga + bG)));
                sp = (e2 + bEp) / (1.f + __expf(-(g2 + bGp)));
            }
        }
#pragma unroll
        for (int off = 16; off >= 1; off >>= 1) {
            se += __shfl_xor_sync(0xffffffffu, se, off);
            sp += __shfl_xor_sync(0xffffffffu, sp, off);
        }
        if (lane == 0) { sRed[w] = se; sRed[16 + w] = sp; }
        __syncthreads();
        if (t == 0) {
            float a = 0.f, p2 = 0.f;
            for (int i = 0; i < 16; i++) { a += sRed[i]; p2 += sRed[16 + i]; }
            atomicAdd(&g_acc[b],     a);
            atomicAdd(&g_acc[4 + b], p2);
        }
    }

    // ---- phase 4 (fused lig): O[cc][e] = sum_np sT[np][cc] * pocket[b][np][e]
    // warp w owns cc = 2w, 2w+1; lane owns e = 4*lane..4*lane+3
    {
        ull acc[4] = {0ull,0ull,0ull,0ull};
        for (int c0 = 0; c0 < 8; c0++) {
            __syncthreads();    // previous chunk fully consumed (also covers first-entry aliasing)
            const float4* Pg = reinterpret_cast<const float4*>(
                pocket + ((size_t)b * NP_ + c0 * 64) * E_);
            float4* sP4 = reinterpret_cast<float4*>(sP);
#pragma unroll
            for (int u = 0; u < 4; u++) sP4[t + 512*u] = Pg[t + 512*u];
            __syncthreads();

#pragma unroll 4
            for (int np = 0; np < 64; np++) {
                float2 a2 = *reinterpret_cast<const float2*>(&sT[(c0*64 + np)*34 + w*2]);
                ulonglong2 pv = *reinterpret_cast<const ulonglong2*>(&sP[np*128 + lane*4]);
                ull d0 = pack2(a2.x, a2.x);
                FMA2(acc[0], d0, pv.x); FMA2(acc[1], d0, pv.y);
                ull d1 = pack2(a2.y, a2.y);
                FMA2(acc[2], d1, pv.x); FMA2(acc[3], d1, pv.y);
            }
        }
#pragma unroll
        for (int j = 0; j < 2; j++) {
            float4 o;
            unpack2(o.x, o.y, acc[2*j]);
            unpack2(o.z, o.w, acc[2*j + 1]);
            int cc = w*2 + j;
            reinterpret_cast<float4*>(
                g_lig + (((size_t)b * C_ + cc) * NC_ + nc) * E_)[lane] = o;
        }
    }
}

// ---------------- K5: split-K GEMM partials -------------------------------
// grid (2 eo-halves, 16 M-tiles of 64 rows, 8 K-chunks of 4 cc), 256 threads.
__global__ void __launch_bounds__(256) k_out(const float* __restrict__ Wout)
{
    extern __shared__ float smem[];
    float* sAt = smem;            // [128 e][64 r]  (A transposed)
    float* sB  = smem + 8192;     // [128 e][64 eo]

    int t   = threadIdx.x;
    int eo0 = blockIdx.x * 64;
    int y   = blockIdx.y;         // M tile: rows y*64 .. y*64+63
    int kc  = blockIdx.z;         // cc group: 4*kc .. 4*kc+3
    int b   = y >> 2;
    int nc0 = (y & 3) * 64;
    int tx  = t & 15, ty = t >> 4;

    ull acc[4][2];
#pragma unroll
    for (int i = 0; i < 4; i++) { acc[i][0] = 0ull; acc[i][1] = 0ull; }

    for (int c = 0; c < 4; c++) {
        int ccg = kc*4 + c;
        const float* Ab = g_lig + (((size_t)b * C_ + ccg) * NC_ + nc0) * E_;
        const float* Bb = Wout + ((size_t)ccg * 128) * E_ + eo0;
        __syncthreads();
#pragma unroll
        for (int p = 0; p < 8; p++) {
            int idx = p*256 + t;
            int r = idx & 63, e4 = idx >> 6;
            float4 v = reinterpret_cast<const float4*>(Ab + (size_t)r * E_)[e4];
            sAt[(4*e4+0)*64 + r] = v.x;
            sAt[(4*e4+1)*64 + r] = v.y;
            sAt[(4*e4+2)*64 + r] = v.z;
            sAt[(4*e4+3)*64 + r] = v.w;
        }
#pragma unroll
        for (int p = 0; p < 8; p++) {
            int idx = p*256 + t;
            int c4 = idx & 15, e = idx >> 4;
            reinterpret_cast<float4*>(sB + e*64)[c4] =
                reinterpret_cast<const float4*>(Bb + (size_t)e * E_)[c4];
        }
        __syncthreads();
#pragma unroll 8
        for (int e = 0; e < 128; e++) {
            float4 av = *reinterpret_cast<const float4*>(&sAt[e*64 + 4*ty]);
            ulonglong2 bv = *reinterpret_cast<const ulonglong2*>(&sB[e*64 + 4*tx]);
            ull d0 = pack2(av.x, av.x);
            FMA2(acc[0][0], d0, bv.x); FMA2(acc[0][1], d0, bv.y);
            ull d1 = pack2(av.y, av.y);
            FMA2(acc[1][0], d1, bv.x); FMA2(acc[1][1], d1, bv.y);
            ull d2 = pack2(av.z, av.z);
            FMA2(acc[2][0], d2, bv.x); FMA2(acc[2][1], d2, bv.y);
            ull d3 = pack2(av.w, av.w);
            FMA2(acc[3][0], d3, bv.x); FMA2(acc[3][1], d3, bv.y);
        }
    }
#pragma unroll
    for (int i = 0; i < 4; i++) {
        float4 o;
        unpack2(o.x, o.y, acc[i][0]);
        unpack2(o.z, o.w, acc[i][1]);
        int row = y*64 + 4*ty + i;
        *reinterpret_cast<float4*>(
            &g_part[((size_t)kc * 1024 + row) * 128 + eo0 + 4*tx]) = o;
    }
}

// ---------------- K5b: reduce split-K partials + bias ---------------------
__global__ void __launch_bounds__(256) k_red(const float* __restrict__ bout,
                                             float* __restrict__ out)
{
    int i4 = blockIdx.x * 256 + threadIdx.x;        // float4 index, < 32768
    const float4* P = reinterpret_cast<const float4*>(g_part);
    float4 s = P[i4];
#pragma unroll
    for (int k = 1; k < 8; k++) {
        float4 v = P[(size_t)k * 32768 + i4];
        s.x += v.x; s.y += v.y; s.z += v.z; s.w += v.w;
    }
    float4 bo = reinterpret_cast<const float4*>(bout)[i4 & 31];
    s.x += bo.x; s.y += bo.y; s.z += bo.z; s.w += bo.w;
    reinterpret_cast<float4*>(out)[i4] = s;
}

// ---------------- K6: finalize affinity / prmsd ---------------------------
__global__ void k_fin(const float* __restrict__ bias,
                      const float* __restrict__ bias_p,
                      float* __restrict__ out)
{
    int t = threadIdx.x;
    if (t < 4) {
        float a = bias[0] + g_acc[t];
        out[131072 + t] = (a > 0.f) ? a : 0.01f * a;
        float p = bias_p[0] + g_acc[4 + t];
        out[131076 + t] = (p > 0.f) ? p : 0.01f * p;
    }
}

// ---------------- launch --------------------------------------------------
extern "C" void kernel_launch(void* const* d_in, const int* in_sizes, int n_in,
                              void* d_out, int out_size)
{
    const float* z      = (const float*)d_in[0];
    const void*  zmask  = d_in[1];
    const float* pocket = (const float*)d_in[2];
    const float* cand   = (const float*)d_in[3];
    const float* Wlin   = (const float*)d_in[4];
    const float* blin   = (const float*)d_in[5];
    const float* Wdis   = (const float*)d_in[6];
    const float* bdis   = (const float*)d_in[7];
    const float* We     = (const float*)d_in[8];
    const float* be     = (const float*)d_in[9];
    const float* Wg     = (const float*)d_in[10];
    const float* bg     = (const float*)d_in[11];
    const float* bias   = (const float*)d_in[12];
    const float* Wep    = (const float*)d_in[13];
    const float* bep    = (const float*)d_in[14];
    const float* Wgp    = (const float*)d_in[15];
    const float* bgp    = (const float*)d_in[16];
    const float* biasp  = (const float*)d_in[17];
    const float* Wout   = (const float*)d_in[18];
    const float* bout   = (const float*)d_in[19];
    float* out = (float*)d_out;

    const int K1_SMEM = 25888 * 4;    // 103552 bytes -> 2 CTAs/SM
    const int KO_SMEM = 16384 * 4;    // 65536 bytes
    cudaFuncSetAttribute(k_main, cudaFuncAttributeMaxDynamicSharedMemorySize, K1_SMEM);
    cudaFuncSetAttribute(k_out,  cudaFuncAttributeMaxDynamicSharedMemorySize, KO_SMEM);

    k_detect<<<1, 32>>>((const unsigned int*)zmask);
    k_disb<<<(B_*NP_*NC_)/8, 256>>>(cand, Wdis, bdis);
    k_main<<<B_*NC_, 512, K1_SMEM>>>(z, zmask, pocket, Wlin, blin,
                                     We, be, Wg, bg, Wep, bep, Wgp, bgp);
    k_out<<<dim3(2, 16, 8), 256, KO_SMEM>>>(Wout);
    k_red<<<128, 256>>>(bout, out);
    k_fin<<<1, 32>>>(bias, biasp, out);
}

// round 8
// speedup vs baseline: 1.0408x; 1.0408x over previous
#include <cuda_runtime.h>
#include <cstdint>
#include <cstddef>

#define B_   4
#define NP_  512
#define NC_  256
#define E_   128
#define C_   32
#define Q_   (NP_*NC_)          // 131072
#define CQ_  (C_*Q_)            // 4194304 per batch
#define NB_  20

typedef unsigned long long ull;

// ---------------- f32x2 packed helpers ------------------------------------
#define FMA2(d, a, b) asm("fma.rn.f32x2 %0, %1, %2, %0;" : "+l"(d) : "l"(a), "l"(b))
__device__ __forceinline__ ull pack2(float x, float y) {
    ull r; asm("mov.b64 %0, {%1, %2};" : "=l"(r) : "f"(x), "f"(y)); return r;
}
__device__ __forceinline__ void unpack2(float& x, float& y, ull v) {
    asm("mov.b64 {%0, %1}, %2;" : "=f"(x), "=f"(y) : "l"(v));
}

// ---------------- scratch (device globals; no allocation) ----------------
__device__ float g_disb[(size_t)B_*NP_*NC_*C_];   // natural [b][np][nc][cc] flat
__device__ float g_lig [(size_t)B_*C_*NC_*E_];    // [b][cc][nc][e]
__device__ float g_part[(size_t)8*1024*128];      // split-K partials for k_out
__device__ float g_acc [8];                       // [0..3]=energy, [4..7]=prmsd
__device__ int   g_mtype;                         // 0=u8, 1=i32, 2=f32

// ---------------- K-1: detect z_mask dtype --------------------------------
__global__ void k_detect(const unsigned int* __restrict__ m)
{
    if (threadIdx.x == 0) {
        bool alli = true, allf = true;
        for (int i = 0; i < 64; i++) {
            unsigned int v = m[i * 97];
            if (!(v == 0u || v == 1u))           alli = false;
            if (!(v == 0u || v == 0x3F800000u))  allf = false;
        }
        g_mtype = alli ? 1 : (allf ? 2 : 0);
    }
}

__device__ __forceinline__ bool mask_at(const void* zm, size_t idx, int mt)
{
    if (mt == 1) return ((const int*)zm)[idx] != 0;
    if (mt == 2) return ((const float*)zm)[idx] != 0.f;
    return ((const unsigned char*)zm)[idx] != 0;
}

// ---------------- K0: distance-bucket bias --------------------------------
__global__ void __launch_bounds__(256) k_disb(const float* __restrict__ cand,
                                              const float* __restrict__ Wd,
                                              const float* __restrict__ bd)
{
    __shared__ float sWd[NB_*32];
    __shared__ float sBd[32];
    int t = threadIdx.x;
    for (int i = t; i < NB_*32; i += 256) sWd[i] = Wd[i];
    if (t < 32) sBd[t] = bd[t];
    __syncthreads();

    int w = t >> 5, lane = t & 31;
    int s = blockIdx.x * 8 + w;              // s = (b*NP+np)*NC+nc
    float x = cand[s];

    float ev = 0.f;
    if (lane < NB_) {
        float v  = (float)(lane + 1) * (15.0f / 21.0f);
        float d  = (x - v) * (21.0f / 15.0f);
        float a  = d + 1.0f;
        float c2 = 1.0f - d;
        if (a > 0.f && c2 > 0.f)
            ev = 8.4335730689f * __expf(-__fdividef(1.f, a) - __fdividef(1.f, c2));
    }
    float acc = sBd[lane];
#pragma unroll
    for (int k = 0; k < NB_; k++) {
        float ek = __shfl_sync(0xffffffffu, ev, k);
        acc = fmaf(ek, sWd[k*32 + lane], acc);
    }
    g_disb[(size_t)s * 32 + lane] = acc;

    if (blockIdx.x == 0 && t < 8) g_acc[t] = 0.f;   // stream-ordered before k_main
}

// ---------------- K1: fused zlin GEMM + softmax + bias + mask + energy + lig
// 512 threads (16 warps). Dynamic smem layout (floats):
//   [0, 12416)      U: phase1 = sWt[32][132] (4224) + sZ[16w][4r][128] (8192)
//                      lig    = sP[64][128]  (8192)
//   [12416, 29824)  sT[512][34]
//   [29824, 29952)  sWE/sWG/sWEP/sWGP (4x32)
//   [29952, 29984)  sRed[32]
__global__ void __launch_bounds__(512) k_main(const float* __restrict__ z,
                                              const void* __restrict__ zmask,
                                              const float* __restrict__ pocket,
                                              const float* __restrict__ Wlin,
                                              const float* __restrict__ blin,
                                              const float* __restrict__ We,  const float* __restrict__ be,
                                              const float* __restrict__ Wg,  const float* __restrict__ bg,
                                              const float* __restrict__ Wep, const float* __restrict__ bep,
                                              const float* __restrict__ Wgp, const float* __restrict__ bgp)
{
    extern __shared__ float smem[];
    float* sWt  = smem;                  // [32][132] transposed W_lin
    float* sZ   = smem + 4224;           // 16 warps x 4 rows x 128
    float* sP   = smem;                  // lig-phase pocket chunk (aliases sWt+sZ)
    float* sT   = smem + 12416;          // [512][34]
    float* sWE  = smem + 29824;
    float* sWG  = sWE + 32;
    float* sWEP = sWG + 32;
    float* sWGP = sWEP + 32;
    float* sRed = sWGP + 32;             // [32]

    int t    = threadIdx.x;
    int b    = blockIdx.x >> 8;
    int nc   = blockIdx.x & 255;
    int w    = t >> 5, lane = t & 31;
    int mt   = g_mtype;

    // transpose-load W_lin: sWt[cc][k] = Wlin[k][cc]
    for (int i = t; i < 32*128; i += 512) {
        int cc = i & 31, k = i >> 5;
        sWt[cc*132 + k] = Wlin[k*32 + cc];
    }
    if (t < 32) { sWE[t] = We[t]; sWG[t] = Wg[t]; sWEP[t] = Wep[t]; sWGP[t] = Wgp[t]; }
    __syncthreads();

    float bl = blin[lane];

    // ---- phase 1: z @ W_lin + b_lin (packed f32x2, 16 warps x 4 rows) ----
    {
        const size_t rstep = (size_t)16 * NC_ * E_;     // np stride of 16
        const float* zp0 = z + (((size_t)b * NP_ + w) * NC_ + nc) * E_;
        const ulonglong2* wrow = reinterpret_cast<const ulonglong2*>(sWt + lane*132);

        float4 cur[4], nxt[4];
#pragma unroll
        for (int j = 0; j < 4; j++)
            cur[j] = reinterpret_cast<const float4*>(zp0 + (size_t)j * rstep)[lane];

        for (int g = 0; g < 8; g++) {
            if (g < 7) {
                const float* zn = zp0 + (size_t)(4*g + 4) * rstep;
#pragma unroll
                for (int j = 0; j < 4; j++)
                    nxt[j] = reinterpret_cast<const float4*>(zn + (size_t)j * rstep)[lane];
            }
#pragma unroll
            for (int j = 0; j < 4; j++)
                reinterpret_cast<float4*>(sZ + (w*4 + j)*128)[lane] = cur[j];
            __syncwarp();

            ull accA[4] = {0ull,0ull,0ull,0ull};
            ull accB[4] = {0ull,0ull,0ull,0ull};
#pragma unroll
            for (int k4 = 0; k4 < 32; k4++) {
                ulonglong2 wv = wrow[k4];
#pragma unroll
                for (int j = 0; j < 4; j++) {
                    ulonglong2 v = reinterpret_cast<const ulonglong2*>(sZ + (w*4 + j)*128)[k4];
                    FMA2(accA[j], v.x, wv.x);
                    FMA2(accB[j], v.y, wv.y);
                }
            }
#pragma unroll
            for (int j = 0; j < 4; j++) {
                float ax, ay, bx, by;
                unpack2(ax, ay, accA[j]);
                unpack2(bx, by, accB[j]);
                int np = w + 16 * (4*g + j);
                sT[np*34 + lane] = (ax + bx) + (ay + by) + bl;
                cur[j] = nxt[j];
            }
            __syncwarp();
        }
    }
    __syncthreads();

    // ---- phase 2: softmax over np, + dis_bias, weird-reshape mask ----
    for (int cr = w; cr < 32; cr += 16) {
        float vv[16];
        float mx = -3.0e38f;
#pragma unroll
        for (int i = 0; i < 16; i++) { vv[i] = sT[(lane + 32*i)*34 + cr]; mx = fmaxf(mx, vv[i]); }
#pragma unroll
        for (int off = 16; off >= 1; off >>= 1) mx = fmaxf(mx, __shfl_xor_sync(0xffffffffu, mx, off));
        float sum = 0.f;
#pragma unroll
        for (int i = 0; i < 16; i++) { vv[i] = __expf(vv[i] - mx); sum += vv[i]; }
#pragma unroll
        for (int off = 16; off >= 1; off >>= 1) sum += __shfl_xor_sync(0xffffffffu, sum, off);
        float inv = 1.0f / sum;

        size_t gb = (size_t)b * CQ_ + (size_t)(cr * NC_ + nc) * NP_;
        size_t mb = (size_t)(cr & 3) * Q_ + (size_t)nc * NP_;
#pragma unroll
        for (int i = 0; i < 16; i++) {
            int np = lane + 32 * i;
            float val = fmaf(vv[i], inv, g_disb[gb + np]);
            if (mask_at(zmask, mb + np, mt)) val = 1e-9f;
            sT[np*34 + cr] = val;
        }
    }
    __syncthreads();

    // ---- phase 3: gated energy heads, accumulate per-b ----
    {
        float bE = be[0], bG = bg[0], bEp = bep[0], bGp = bgp[0];
        float se = 0.f, sp = 0.f;
        {
            int np = t;
            float ea = 0.f, ga = 0.f, e2 = 0.f, g2 = 0.f;
#pragma unroll
            for (int cc = 0; cc < 32; cc++) {
                float v = sT[np*34 + cc];
                ea = fmaf(v, sWE[cc],  ea);
                ga = fmaf(v, sWG[cc],  ga);
                e2 = fmaf(v, sWEP[cc], e2);
                g2 = fmaf(v, sWGP[cc], g2);
            }
            if (mask_at(zmask, ((size_t)b * NP_ + np) * NC_ + nc, mt)) {
                se = (ea + bE)  / (1.f + __expf(-(ga + bG)));
                sp = (e2 + bEp) / (1.f + __expf(-(g2 + bGp)));
            }
        }
#pragma unroll
        for (int off = 16; off >= 1; off >>= 1) {
            se += __shfl_xor_sync(0xffffffffu, se, off);
            sp += __shfl_xor_sync(0xffffffffu, sp, off);
        }
        if (lane == 0) { sRed[w] = se; sRed[16 + w] = sp; }
        __syncthreads();
        if (t == 0) {
            float a = 0.f, p2 = 0.f;
            for (int i = 0; i < 16; i++) { a += sRed[i]; p2 += sRed[16 + i]; }
            atomicAdd(&g_acc[b],     a);
            atomicAdd(&g_acc[4 + b], p2);
        }
    }

    // ---- phase 4 (fused lig): O[cc][e] = sum_np sT[np][cc] * pocket[b][np][e]
    // warp w owns cc = 2w, 2w+1; lane owns e = 4*lane..4*lane+3
    {
        ull acc[4] = {0ull,0ull,0ull,0ull};
        for (int c0 = 0; c0 < 8; c0++) {
            __syncthreads();    // previous chunk fully consumed (also covers first-entry aliasing)
            const float4* Pg = reinterpret_cast<const float4*>(
                pocket + ((size_t)b * NP_ + c0 * 64) * E_);
            float4* sP4 = reinterpret_cast<float4*>(sP);
#pragma unroll
            for (int u = 0; u < 4; u++) sP4[t + 512*u] = Pg[t + 512*u];
            __syncthreads();

#pragma unroll 4
            for (int np = 0; np < 64; np++) {
                float2 a2 = *reinterpret_cast<const float2*>(&sT[(c0*64 + np)*34 + w*2]);
                ulonglong2 pv = *reinterpret_cast<const ulonglong2*>(&sP[np*128 + lane*4]);
                ull d0 = pack2(a2.x, a2.x);
                FMA2(acc[0], d0, pv.x); FMA2(acc[1], d0, pv.y);
                ull d1 = pack2(a2.y, a2.y);
                FMA2(acc[2], d1, pv.x); FMA2(acc[3], d1, pv.y);
            }
        }
#pragma unroll
        for (int j = 0; j < 2; j++) {
            float4 o;
            unpack2(o.x, o.y, acc[2*j]);
            unpack2(o.z, o.w, acc[2*j + 1]);
            int cc = w*2 + j;
            reinterpret_cast<float4*>(
                g_lig + (((size_t)b * C_ + cc) * NC_ + nc) * E_)[lane] = o;
        }
    }
}

// ---------------- K5: split-K GEMM partials -------------------------------
// grid (2 eo-halves, 16 M-tiles of 64 rows, 8 K-chunks of 4 cc), 256 threads.
__global__ void __launch_bounds__(256) k_out(const float* __restrict__ Wout)
{
    extern __shared__ float smem[];
    float* sAt = smem;            // [128 e][64 r]  (A transposed)
    float* sB  = smem + 8192;     // [128 e][64 eo]

    int t   = threadIdx.x;
    int eo0 = blockIdx.x * 64;
    int y   = blockIdx.y;         // M tile: rows y*64 .. y*64+63
    int kc  = blockIdx.z;         // cc group: 4*kc .. 4*kc+3
    int b   = y >> 2;
    int nc0 = (y & 3) * 64;
    int tx  = t & 15, ty = t >> 4;

    ull acc[4][2];
#pragma unroll
    for (int i = 0; i < 4; i++) { acc[i][0] = 0ull; acc[i][1] = 0ull; }

    for (int c = 0; c < 4; c++) {
        int ccg = kc*4 + c;
        const float* Ab = g_lig + (((size_t)b * C_ + ccg) * NC_ + nc0) * E_;
        const float* Bb = Wout + ((size_t)ccg * 128) * E_ + eo0;
        __syncthreads();
#pragma unroll
        for (int p = 0; p < 8; p++) {
            int idx = p*256 + t;
            int r = idx & 63, e4 = idx >> 6;
            float4 v = reinterpret_cast<const float4*>(Ab + (size_t)r * E_)[e4];
            sAt[(4*e4+0)*64 + r] = v.x;
            sAt[(4*e4+1)*64 + r] = v.y;
            sAt[(4*e4+2)*64 + r] = v.z;
            sAt[(4*e4+3)*64 + r] = v.w;
        }
#pragma unroll
        for (int p = 0; p < 8; p++) {
            int idx = p*256 + t;
            int c4 = idx & 15, e = idx >> 4;
            reinterpret_cast<float4*>(sB + e*64)[c4] =
                reinterpret_cast<const float4*>(Bb + (size_t)e * E_)[c4];
        }
        __syncthreads();
#pragma unroll 8
        for (int e = 0; e < 128; e++) {
            float4 av = *reinterpret_cast<const float4*>(&sAt[e*64 + 4*ty]);
            ulonglong2 bv = *reinterpret_cast<const ulonglong2*>(&sB[e*64 + 4*tx]);
            ull d0 = pack2(av.x, av.x);
            FMA2(acc[0][0], d0, bv.x); FMA2(acc[0][1], d0, bv.y);
            ull d1 = pack2(av.y, av.y);
            FMA2(acc[1][0], d1, bv.x); FMA2(acc[1][1], d1, bv.y);
            ull d2 = pack2(av.z, av.z);
            FMA2(acc[2][0], d2, bv.x); FMA2(acc[2][1], d2, bv.y);
            ull d3 = pack2(av.w, av.w);
            FMA2(acc[3][0], d3, bv.x); FMA2(acc[3][1], d3, bv.y);
        }
    }
#pragma unroll
    for (int i = 0; i < 4; i++) {
        float4 o;
        unpack2(o.x, o.y, acc[i][0]);
        unpack2(o.z, o.w, acc[i][1]);
        int row = y*64 + 4*ty + i;
        *reinterpret_cast<float4*>(
            &g_part[((size_t)kc * 1024 + row) * 128 + eo0 + 4*tx]) = o;
    }
}

// ---------------- K5b: reduce split-K partials + bias ---------------------
__global__ void __launch_bounds__(256) k_red(const float* __restrict__ bout,
                                             float* __restrict__ out)
{
    int i4 = blockIdx.x * 256 + threadIdx.x;        // float4 index, < 32768
    const float4* P = reinterpret_cast<const float4*>(g_part);
    float4 s = P[i4];
#pragma unroll
    for (int k = 1; k < 8; k++) {
        float4 v = P[(size_t)k * 32768 + i4];
        s.x += v.x; s.y += v.y; s.z += v.z; s.w += v.w;
    }
    float4 bo = reinterpret_cast<const float4*>(bout)[i4 & 31];
    s.x += bo.x; s.y += bo.y; s.z += bo.z; s.w += bo.w;
    reinterpret_cast<float4*>(out)[i4] = s;
}

// ---------------- K6: finalize affinity / prmsd ---------------------------
__global__ void k_fin(const float* __restrict__ bias,
                      const float* __restrict__ bias_p,
                      float* __restrict__ out)
{
    int t = threadIdx.x;
    if (t < 4) {
        float a = bias[0] + g_acc[t];
        out[131072 + t] = (a > 0.f) ? a : 0.01f * a;
        float p = bias_p[0] + g_acc[4 + t];
        out[131076 + t] = (p > 0.f) ? p : 0.01f * p;
    }
}

// ---------------- launch --------------------------------------------------
extern "C" void kernel_launch(void* const* d_in, const int* in_sizes, int n_in,
                              void* d_out, int out_size)
{
    const float* z      = (const float*)d_in[0];
    const void*  zmask  = d_in[1];
    const float* pocket = (const float*)d_in[2];
    const float* cand   = (const float*)d_in[3];
    const float* Wlin   = (const float*)d_in[4];
    const float* blin   = (const float*)d_in[5];
    const float* Wdis   = (const float*)d_in[6];
    const float* bdis   = (const float*)d_in[7];
    const float* We     = (const float*)d_in[8];
    const float* be     = (const float*)d_in[9];
    const float* Wg     = (const float*)d_in[10];
    const float* bg     = (const float*)d_in[11];
    const float* bias   = (const float*)d_in[12];
    const float* Wep    = (const float*)d_in[13];
    const float* bep    = (const float*)d_in[14];
    const float* Wgp    = (const float*)d_in[15];
    const float* bgp    = (const float*)d_in[16];
    const float* biasp  = (const float*)d_in[17];
    const float* Wout   = (const float*)d_in[18];
    const float* bout   = (const float*)d_in[19];
    float* out = (float*)d_out;

    const int K1_SMEM = 29984 * 4;    // 119936 bytes
    const int KO_SMEM = 16384 * 4;    // 65536 bytes
    cudaFuncSetAttribute(k_main, cudaFuncAttributeMaxDynamicSharedMemorySize, K1_SMEM);
    cudaFuncSetAttribute(k_out,  cudaFuncAttributeMaxDynamicSharedMemorySize, KO_SMEM);

    // launch index:            0         1       2 (pad so k_main lands at 3)
    k_detect<<<1, 32>>>((const unsigned int*)zmask);
    k_disb<<<(B_*NP_*NC_)/8, 256>>>(cand, Wdis, bdis);
    k_detect<<<1, 32>>>((const unsigned int*)zmask);   // idempotent pad launch
    k_main<<<B_*NC_, 512, K1_SMEM>>>(z, zmask, pocket, Wlin, blin,
                                     We, be, Wg, bg, Wep, bep, Wgp, bgp);
    k_out<<<dim3(2, 16, 8), 256, KO_SMEM>>>(Wout);
    k_red<<<128, 256>>>(bout, out);
    k_fin<<<1, 32>>>(bias, biasp, out);
}

// round 10
// speedup vs baseline: 1.0712x; 1.0292x over previous
#include <cuda_runtime.h>
#include <cstdint>
#include <cstddef>

#define B_   4
#define NP_  512
#define NC_  256
#define E_   128
#define C_   32
#define Q_   (NP_*NC_)          // 131072
#define CQ_  (C_*Q_)            // 4194304 per batch
#define NB_  20

typedef unsigned long long ull;

// ---------------- f32x2 packed helpers ------------------------------------
#define FMA2(d, a, b) asm("fma.rn.f32x2 %0, %1, %2, %0;" : "+l"(d) : "l"(a), "l"(b))
__device__ __forceinline__ ull pack2(float x, float y) {
    ull r; asm("mov.b64 %0, {%1, %2};" : "=l"(r) : "f"(x), "f"(y)); return r;
}
__device__ __forceinline__ void unpack2(float& x, float& y, ull v) {
    asm("mov.b64 {%0, %1}, %2;" : "=f"(x), "=f"(y) : "l"(v));
}

// ---------------- scratch (device globals; no allocation) ----------------
__device__ float g_disb[(size_t)B_*NP_*NC_*C_];   // natural [b][np][nc][cc] flat
__device__ float g_lig [(size_t)B_*C_*NC_*E_];    // [b][cc][nc][e]
__device__ float g_part[(size_t)8*1024*128];      // split-K partials for k_out
__device__ float g_acc [8];                       // [0..3]=energy, [4..7]=prmsd
__device__ int   g_mtype;                         // 0=u8, 1=i32, 2=f32

// ---------------- K-1: detect z_mask dtype --------------------------------
__global__ void k_detect(const unsigned int* __restrict__ m)
{
    if (threadIdx.x == 0) {
        bool alli = true, allf = true;
        for (int i = 0; i < 64; i++) {
            unsigned int v = m[i * 97];
            if (!(v == 0u || v == 1u))           alli = false;
            if (!(v == 0u || v == 0x3F800000u))  allf = false;
        }
        g_mtype = alli ? 1 : (allf ? 2 : 0);
    }
}

__device__ __forceinline__ bool mask_at(const void* zm, size_t idx, int mt)
{
    if (mt == 1) return ((const int*)zm)[idx] != 0;
    if (mt == 2) return ((const float*)zm)[idx] != 0.f;
    return ((const unsigned char*)zm)[idx] != 0;
}

// ---------------- K0: distance-bucket bias --------------------------------
__global__ void __launch_bounds__(256) k_disb(const float* __restrict__ cand,
                                              const float* __restrict__ Wd,
                                              const float* __restrict__ bd)
{
    __shared__ float sWd[NB_*32];
    __shared__ float sBd[32];
    int t = threadIdx.x;
    for (int i = t; i < NB_*32; i += 256) sWd[i] = Wd[i];
    if (t < 32) sBd[t] = bd[t];
    __syncthreads();

    int w = t >> 5, lane = t & 31;
    int s = blockIdx.x * 8 + w;              // s = (b*NP+np)*NC+nc
    float x = cand[s];

    float ev = 0.f;
    if (lane < NB_) {
        float v  = (float)(lane + 1) * (15.0f / 21.0f);
        float d  = (x - v) * (21.0f / 15.0f);
        float a  = d + 1.0f;
        float c2 = 1.0f - d;
        if (a > 0.f && c2 > 0.f)
            ev = 8.4335730689f * __expf(-__fdividef(1.f, a) - __fdividef(1.f, c2));
    }
    float acc = sBd[lane];
#pragma unroll
    for (int k = 0; k < NB_; k++) {
        float ek = __shfl_sync(0xffffffffu, ev, k);
        acc = fmaf(ek, sWd[k*32 + lane], acc);
    }
    g_disb[(size_t)s * 32 + lane] = acc;

    if (blockIdx.x == 0 && t < 8) g_acc[t] = 0.f;   // stream-ordered before k_main
}

// ---------------- K1: fused zlin GEMM + softmax + bias + mask + energy + lig
// 512 threads (16 warps). Dynamic smem layout (floats):
//   [0, 4224)       sWt[32][132] transposed W_lin        (phase 1)
//   [4224, 20608)   sZ: 16 warps x 8 rows x 128          (phase 1)
//   [0, 8192)       sP[64][128] pocket chunk             (phase 4, aliases)
//   [20608, 39040)  sT[512][36]
//   [39040, 39168)  sWE/sWG/sWEP/sWGP (4x32)
//   [39168, 39200)  sRed[32]
// Total 39200 floats = 156800 B.
__global__ void __launch_bounds__(512) k_main(const float* __restrict__ z,
                                              const void* __restrict__ zmask,
                                              const float* __restrict__ pocket,
                                              const float* __restrict__ Wlin,
                                              const float* __restrict__ blin,
                                              const float* __restrict__ We,  const float* __restrict__ be,
                                              const float* __restrict__ Wg,  const float* __restrict__ bg,
                                              const float* __restrict__ Wep, const float* __restrict__ bep,
                                              const float* __restrict__ Wgp, const float* __restrict__ bgp)
{
    extern __shared__ float smem[];
    float* sWt  = smem;                  // [32][132] transposed W_lin
    float* sZ   = smem + 4224;           // 16 warps x 8 rows x 128
    float* sP   = smem;                  // lig-phase pocket chunk (aliases)
    float* sT   = smem + 20608;          // [512][36]
    float* sWE  = smem + 39040;
    float* sWG  = sWE + 32;
    float* sWEP = sWG + 32;
    float* sWGP = sWEP + 32;
    float* sRed = sWGP + 32;             // [32]

    int t    = threadIdx.x;
    int b    = blockIdx.x >> 8;
    int nc   = blockIdx.x & 255;
    int w    = t >> 5, lane = t & 31;
    int mt   = g_mtype;

    // transpose-load W_lin: sWt[cc][k] = Wlin[k][cc]
    for (int i = t; i < 32*128; i += 512) {
        int cc = i & 31, k = i >> 5;
        sWt[cc*132 + k] = Wlin[k*32 + cc];
    }
    if (t < 32) { sWE[t] = We[t]; sWG[t] = Wg[t]; sWEP[t] = Wep[t]; sWGP[t] = Wgp[t]; }
    __syncthreads();

    float bl = blin[lane];

    // ---- phase 1: z @ W_lin + b_lin (packed f32x2, 8 rows per wrow pass) ----
    {
        const size_t rstep = (size_t)16 * NC_ * E_;     // np stride of 16
        const float* zp0 = z + (((size_t)b * NP_ + w) * NC_ + nc) * E_;
        const ulonglong2* wrow = reinterpret_cast<const ulonglong2*>(sWt + lane*132);
        float* myZ = sZ + w*8*128;

        for (int g = 0; g < 4; g++) {
            const float* zg = zp0 + (size_t)(8*g) * rstep;
            float4 cur[8];
#pragma unroll
            for (int j = 0; j < 8; j++)
                cur[j] = reinterpret_cast<const float4*>(zg + (size_t)j * rstep)[lane];
#pragma unroll
            for (int j = 0; j < 8; j++)
                reinterpret_cast<float4*>(myZ + j*128)[lane] = cur[j];
            __syncwarp();

            ull accA[8], accB[8];
#pragma unroll
            for (int j = 0; j < 8; j++) { accA[j] = 0ull; accB[j] = 0ull; }
#pragma unroll
            for (int k4 = 0; k4 < 32; k4++) {
                ulonglong2 wv = wrow[k4];
#pragma unroll
                for (int j = 0; j < 8; j++) {
                    ulonglong2 v = reinterpret_cast<const ulonglong2*>(myZ + j*128)[k4];
                    FMA2(accA[j], v.x, wv.x);
                    FMA2(accB[j], v.y, wv.y);
                }
            }
#pragma unroll
            for (int j = 0; j < 8; j++) {
                float ax, ay, bx, by;
                unpack2(ax, ay, accA[j]);
                unpack2(bx, by, accB[j]);
                int np = w + 16 * (8*g + j);
                sT[np*36 + lane] = (ax + bx) + (ay + by) + bl;
            }
            __syncwarp();
        }
    }
    __syncthreads();

    // ---- phase 2: softmax over np, + dis_bias, weird-reshape mask ----
    for (int cr = w; cr < 32; cr += 16) {
        float vv[16];
        float mx = -3.0e38f;
#pragma unroll
        for (int i = 0; i < 16; i++) { vv[i] = sT[(lane + 32*i)*36 + cr]; mx = fmaxf(mx, vv[i]); }
#pragma unroll
        for (int off = 16; off >= 1; off >>= 1) mx = fmaxf(mx, __shfl_xor_sync(0xffffffffu, mx, off));
        float sum = 0.f;
#pragma unroll
        for (int i = 0; i < 16; i++) { vv[i] = __expf(vv[i] - mx); sum += vv[i]; }
#pragma unroll
        for (int off = 16; off >= 1; off >>= 1) sum += __shfl_xor_sync(0xffffffffu, sum, off);
        float inv = 1.0f / sum;

        size_t gb = (size_t)b * CQ_ + (size_t)(cr * NC_ + nc) * NP_;
        size_t mb = (size_t)(cr & 3) * Q_ + (size_t)nc * NP_;
#pragma unroll
        for (int i = 0; i < 16; i++) {
            int np = lane + 32 * i;
            float val = fmaf(vv[i], inv, g_disb[gb + np]);
            if (mask_at(zmask, mb + np, mt)) val = 1e-9f;
            sT[np*36 + cr] = val;
        }
    }
    __syncthreads();

    // ---- phase 3: gated energy heads, accumulate per-b ----
    {
        float bE = be[0], bG = bg[0], bEp = bep[0], bGp = bgp[0];
        float se = 0.f, sp = 0.f;
        {
            int np = t;
            float ea = 0.f, ga = 0.f, e2 = 0.f, g2 = 0.f;
#pragma unroll
            for (int cc = 0; cc < 32; cc++) {
                float v = sT[np*36 + cc];
                ea = fmaf(v, sWE[cc],  ea);
                ga = fmaf(v, sWG[cc],  ga);
                e2 = fmaf(v, sWEP[cc], e2);
                g2 = fmaf(v, sWGP[cc], g2);
            }
            if (mask_at(zmask, ((size_t)b * NP_ + np) * NC_ + nc, mt)) {
                se = (ea + bE)  / (1.f + __expf(-(ga + bG)));
                sp = (e2 + bEp) / (1.f + __expf(-(g2 + bGp)));
            }
        }
#pragma unroll
        for (int off = 16; off >= 1; off >>= 1) {
            se += __shfl_xor_sync(0xffffffffu, se, off);
            sp += __shfl_xor_sync(0xffffffffu, sp, off);
        }
        if (lane == 0) { sRed[w] = se; sRed[16 + w] = sp; }
        __syncthreads();
        if (t == 0) {
            float a = 0.f, p2 = 0.f;
            for (int i = 0; i < 16; i++) { a += sRed[i]; p2 += sRed[16 + i]; }
            atomicAdd(&g_acc[b],     a);
            atomicAdd(&g_acc[4 + b], p2);
        }
    }

    // ---- phase 4 (fused lig): O[cc][e] = sum_np sT[np][cc] * pocket[b][np][e]
    // warp w -> e-slice [8w, 8w+8); lane: lc = lane&7 -> cc-quad 4lc..4lc+3,
    // le = lane>>3 -> e-pair e0 = 8w+2le. Thread tile: 4cc x 2e, acc as cc-pairs.
    {
        int lc = lane & 7, le = lane >> 3;
        int e0 = w*8 + le*2;
        ull acc[4] = {0ull,0ull,0ull,0ull};   // [e][ccpair]: 0=cp0@e0 1=cp1@e0 2=cp0@e1 3=cp1@e1

        for (int c0 = 0; c0 < 8; c0++) {
            __syncthreads();    // previous chunk fully consumed (covers aliasing too)
            const float4* Pg = reinterpret_cast<const float4*>(
                pocket + ((size_t)b * NP_ + c0 * 64) * E_);
            float4* sP4 = reinterpret_cast<float4*>(sP);
#pragma unroll
            for (int u = 0; u < 4; u++) sP4[t + 512*u] = Pg[t + 512*u];
            __syncthreads();

            const float* sTc = sT + (c0*64)*36 + lc*4;
#pragma unroll 4
            for (int np = 0; np < 64; np++) {
                ulonglong2 a4 = *reinterpret_cast<const ulonglong2*>(sTc + np*36);
                float2 pv = *reinterpret_cast<const float2*>(&sP[np*128 + e0]);
                ull d0 = pack2(pv.x, pv.x);
                ull d1 = pack2(pv.y, pv.y);
                FMA2(acc[0], a4.x, d0);
                FMA2(acc[1], a4.y, d0);
                FMA2(acc[2], a4.x, d1);
                FMA2(acc[3], a4.y, d1);
            }
        }
#pragma unroll
        for (int cp = 0; cp < 2; cp++) {
            float x0, x1, y0, y1;
            unpack2(x0, x1, acc[cp]);       // cc 4lc+2cp, 4lc+2cp+1 @ e0
            unpack2(y0, y1, acc[2 + cp]);   // same cc @ e0+1
            int cc0 = lc*4 + 2*cp;
            *reinterpret_cast<float2*>(
                g_lig + (((size_t)b * C_ + cc0) * NC_ + nc) * E_ + e0) = make_float2(x0, y0);
            *reinterpret_cast<float2*>(
                g_lig + (((size_t)b * C_ + cc0 + 1) * NC_ + nc) * E_ + e0) = make_float2(x1, y1);
        }
    }
}

// ---------------- K5: split-K GEMM partials -------------------------------
// grid (2 eo-halves, 16 M-tiles of 64 rows, 8 K-chunks of 4 cc), 256 threads.
__global__ void __launch_bounds__(256) k_out(const float* __restrict__ Wout)
{
    extern __shared__ float smem[];
    float* sAt = smem;            // [128 e][64 r]  (A transposed)
    float* sB  = smem + 8192;     // [128 e][64 eo]

    int t   = threadIdx.x;
    int eo0 = blockIdx.x * 64;
    int y   = blockIdx.y;         // M tile: rows y*64 .. y*64+63
    int kc  = blockIdx.z;         // cc group: 4*kc .. 4*kc+3
    int b   = y >> 2;
    int nc0 = (y & 3) * 64;
    int tx  = t & 15, ty = t >> 4;

    ull acc[4][2];
#pragma unroll
    for (int i = 0; i < 4; i++) { acc[i][0] = 0ull; acc[i][1] = 0ull; }

    for (int c = 0; c < 4; c++) {
        int ccg = kc*4 + c;
        const float* Ab = g_lig + (((size_t)b * C_ + ccg) * NC_ + nc0) * E_;
        const float* Bb = Wout + ((size_t)ccg * 128) * E_ + eo0;
        __syncthreads();
#pragma unroll
        for (int p = 0; p < 8; p++) {
            int idx = p*256 + t;
            int r = idx & 63, e4 = idx >> 6;
            float4 v = reinterpret_cast<const float4*>(Ab + (size_t)r * E_)[e4];
            sAt[(4*e4+0)*64 + r] = v.x;
            sAt[(4*e4+1)*64 + r] = v.y;
            sAt[(4*e4+2)*64 + r] = v.z;
            sAt[(4*e4+3)*64 + r] = v.w;
        }
#pragma unroll
        for (int p = 0; p < 8; p++) {
            int idx = p*256 + t;
            int c4 = idx & 15, e = idx >> 4;
            reinterpret_cast<float4*>(sB + e*64)[c4] =
                reinterpret_cast<const float4*>(Bb + (size_t)e * E_)[c4];
        }
        __syncthreads();
#pragma unroll 8
        for (int e = 0; e < 128; e++) {
            float4 av = *reinterpret_cast<const float4*>(&sAt[e*64 + 4*ty]);
            ulonglong2 bv = *reinterpret_cast<const ulonglong2*>(&sB[e*64 + 4*tx]);
            ull d0 = pack2(av.x, av.x);
            FMA2(acc[0][0], d0, bv.x); FMA2(acc[0][1], d0, bv.y);
            ull d1 = pack2(av.y, av.y);
            FMA2(acc[1][0], d1, bv.x); FMA2(acc[1][1], d1, bv.y);
            ull d2 = pack2(av.z, av.z);
            FMA2(acc[2][0], d2, bv.x); FMA2(acc[2][1], d2, bv.y);
            ull d3 = pack2(av.w, av.w);
            FMA2(acc[3][0], d3, bv.x); FMA2(acc[3][1], d3, bv.y);
        }
    }
#pragma unroll
    for (int i = 0; i < 4; i++) {
        float4 o;
        unpack2(o.x, o.y, acc[i][0]);
        unpack2(o.z, o.w, acc[i][1]);
        int row = y*64 + 4*ty + i;
        *reinterpret_cast<float4*>(
            &g_part[((size_t)kc * 1024 + row) * 128 + eo0 + 4*tx]) = o;
    }
}

// ---------------- K5b: reduce split-K partials + bias ---------------------
__global__ void __launch_bounds__(256) k_red(const float* __restrict__ bout,
                                             float* __restrict__ out)
{
    int i4 = blockIdx.x * 256 + threadIdx.x;        // float4 index, < 32768
    const float4* P = reinterpret_cast<const float4*>(g_part);
    float4 s = P[i4];
#pragma unroll
    for (int k = 1; k < 8; k++) {
        float4 v = P[(size_t)k * 32768 + i4];
        s.x += v.x; s.y += v.y; s.z += v.z; s.w += v.w;
    }
    float4 bo = reinterpret_cast<const float4*>(bout)[i4 & 31];
    s.x += bo.x; s.y += bo.y; s.z += bo.z; s.w += bo.w;
    reinterpret_cast<float4*>(out)[i4] = s;
}

// ---------------- K6: finalize affinity / prmsd ---------------------------
__global__ void k_fin(const float* __restrict__ bias,
                      const float* __restrict__ bias_p,
                      float* __restrict__ out)
{
    int t = threadIdx.x;
    if (t < 4) {
        float a = bias[0] + g_acc[t];
        out[131072 + t] = (a > 0.f) ? a : 0.01f * a;
        float p = bias_p[0] + g_acc[4 + t];
        out[131076 + t] = (p > 0.f) ? p : 0.01f * p;
    }
}

// ---------------- launch --------------------------------------------------
extern "C" void kernel_launch(void* const* d_in, const int* in_sizes, int n_in,
                              void* d_out, int out_size)
{
    const float* z      = (const float*)d_in[0];
    const void*  zmask  = d_in[1];
    const float* pocket = (const float*)d_in[2];
    const float* cand   = (const float*)d_in[3];
    const float* Wlin   = (const float*)d_in[4];
    const float* blin   = (const float*)d_in[5];
    const float* Wdis   = (const float*)d_in[6];
    const float* bdis   = (const float*)d_in[7];
    const float* We     = (const float*)d_in[8];
    const float* be     = (const float*)d_in[9];
    const float* Wg     = (const float*)d_in[10];
    const float* bg     = (const float*)d_in[11];
    const float* bias   = (const float*)d_in[12];
    const float* Wep    = (const float*)d_in[13];
    const float* bep    = (const float*)d_in[14];
    const float* Wgp    = (const float*)d_in[15];
    const float* bgp    = (const float*)d_in[16];
    const float* biasp  = (const float*)d_in[17];
    const float* Wout   = (const float*)d_in[18];
    const float* bout   = (const float*)d_in[19];
    float* out = (float*)d_out;

    const int K1_SMEM = 39200 * 4;    // 156800 bytes
    const int KO_SMEM = 16384 * 4;    // 65536 bytes
    cudaFuncSetAttribute(k_main, cudaFuncAttributeMaxDynamicSharedMemorySize, K1_SMEM);
    cudaFuncSetAttribute(k_out,  cudaFuncAttributeMaxDynamicSharedMemorySize, KO_SMEM);

    // launch index:            0         1       2 (pad so k_main lands at 3)
    k_detect<<<1, 32>>>((const unsigned int*)zmask);
    k_disb<<<(B_*NP_*NC_)/8, 256>>>(cand, Wdis, bdis);
    k_detect<<<1, 32>>>((const unsigned int*)zmask);   // idempotent pad launch
    k_main<<<B_*NC_, 512, K1_SMEM>>>(z, zmask, pocket, Wlin, blin,
                                     We, be, Wg, bg, Wep, bep, Wgp, bgp);
    k_out<<<dim3(2, 16, 8), 256, KO_SMEM>>>(Wout);
    k_red<<<128, 256>>>(bout, out);
    k_fin<<<1, 32>>>(bias, biasp, out);
}

// round 11
// speedup vs baseline: 1.1173x; 1.0430x over previous
#include <cuda_runtime.h>
#include <cstdint>
#include <cstddef>

#define B_   4
#define NP_  512
#define NC_  256
#define E_   128
#define C_   32
#define Q_   (NP_*NC_)          // 131072
#define CQ_  (C_*Q_)            // 4194304 per batch
#define NB_  20

typedef unsigned long long ull;

// ---------------- f32x2 packed helpers ------------------------------------
#define FMA2(d, a, b) asm("fma.rn.f32x2 %0, %1, %2, %0;" : "+l"(d) : "l"(a), "l"(b))
__device__ __forceinline__ ull pack2(float x, float y) {
    ull r; asm("mov.b64 %0, {%1, %2};" : "=l"(r) : "f"(x), "f"(y)); return r;
}
__device__ __forceinline__ void unpack2(float& x, float& y, ull v) {
    asm("mov.b64 {%0, %1}, %2;" : "=f"(x), "=f"(y) : "l"(v));
}

// ---------------- scratch (device globals; no allocation) ----------------
__device__ float g_disb[(size_t)B_*NP_*NC_*C_];   // natural [b][np][nc][cc] flat
__device__ float g_lig [(size_t)B_*C_*NC_*E_];    // [b][cc][nc][e]
__device__ float g_part[(size_t)16*1024*128];     // split-K partials for k_out
__device__ float g_acc [8];                       // [0..3]=energy, [4..7]=prmsd
__device__ int   g_mtype;                         // 0=u8, 1=i32, 2=f32

// ---------------- K-1: detect z_mask dtype --------------------------------
__global__ void k_detect(const unsigned int* __restrict__ m)
{
    if (threadIdx.x == 0) {
        bool alli = true, allf = true;
        for (int i = 0; i < 64; i++) {
            unsigned int v = m[i * 97];
            if (!(v == 0u || v == 1u))           alli = false;
            if (!(v == 0u || v == 0x3F800000u))  allf = false;
        }
        g_mtype = alli ? 1 : (allf ? 2 : 0);
    }
}

__device__ __forceinline__ bool mask_at(const void* zm, size_t idx, int mt)
{
    if (mt == 1) return ((const int*)zm)[idx] != 0;
    if (mt == 2) return ((const float*)zm)[idx] != 0.f;
    return ((const unsigned char*)zm)[idx] != 0;
}

// ---------------- K0: distance-bucket bias --------------------------------
__global__ void __launch_bounds__(256) k_disb(const float* __restrict__ cand,
                                              const float* __restrict__ Wd,
                                              const float* __restrict__ bd)
{
    __shared__ float sWd[NB_*32];
    __shared__ float sBd[32];
    int t = threadIdx.x;
    for (int i = t; i < NB_*32; i += 256) sWd[i] = Wd[i];
    if (t < 32) sBd[t] = bd[t];
    __syncthreads();

    int w = t >> 5, lane = t & 31;
    int s = blockIdx.x * 8 + w;              // s = (b*NP+np)*NC+nc
    float x = cand[s];

    float ev = 0.f;
    if (lane < NB_) {
        float v  = (float)(lane + 1) * (15.0f / 21.0f);
        float d  = (x - v) * (21.0f / 15.0f);
        float a  = d + 1.0f;
        float c2 = 1.0f - d;
        if (a > 0.f && c2 > 0.f)
            ev = 8.4335730689f * __expf(-__fdividef(1.f, a) - __fdividef(1.f, c2));
    }
    float acc = sBd[lane];
#pragma unroll
    for (int k = 0; k < NB_; k++) {
        float ek = __shfl_sync(0xffffffffu, ev, k);
        acc = fmaf(ek, sWd[k*32 + lane], acc);
    }
    g_disb[(size_t)s * 32 + lane] = acc;

    if (blockIdx.x == 0 && t < 8) g_acc[t] = 0.f;   // stream-ordered before k_main
}

// ---------------- K1: fused zlin GEMM + softmax + bias + mask + energy + lig
// 512 threads (16 warps). Dynamic smem layout (floats):
//   [0, 4096)       sW3: W_lin as 16B k-quad chunks [32 k4][2 half][16 lcc][4]
//   [4096, 20480)   sZ: 16 warps x 8 rows x 128          (phase 1)
//   [0, 8192)       sP[64][128] pocket chunk             (phase 4, aliases)
//   [20480, 38912)  sT[512][36]
//   [38912, 39040)  sWE/sWG/sWEP/sWGP (4x32)
//   [39040, 39072)  sRed[32]
// Total 39072 floats = 156288 B.
__global__ void __launch_bounds__(512) k_main(const float* __restrict__ z,
                                              const void* __restrict__ zmask,
                                              const float* __restrict__ pocket,
                                              const float* __restrict__ Wlin,
                                              const float* __restrict__ blin,
                                              const float* __restrict__ We,  const float* __restrict__ be,
                                              const float* __restrict__ Wg,  const float* __restrict__ bg,
                                              const float* __restrict__ Wep, const float* __restrict__ bep,
                                              const float* __restrict__ Wgp, const float* __restrict__ bgp)
{
    extern __shared__ float smem[];
    float* sW3  = smem;                  // 4096: chunked W_lin
    float* sZ   = smem + 4096;           // 16 warps x 8 rows x 128
    float* sP   = smem;                  // lig-phase pocket chunk (aliases)
    float* sT   = smem + 20480;          // [512][36]
    float* sWE  = smem + 38912;
    float* sWG  = sWE + 32;
    float* sWEP = sWG + 32;
    float* sWGP = sWEP + 32;
    float* sRed = sWGP + 32;             // [32]

    int t    = threadIdx.x;
    int b    = blockIdx.x >> 8;
    int nc   = blockIdx.x & 255;
    int w    = t >> 5, lane = t & 31;
    int mt   = g_mtype;

    // Build sW3: chunk index (k4*2 + half)*16 + lcc holds W[2*lcc+half][4k4..4k4+3]
    // i = (((k4*2 + half)*16 + lcc)*4 + w4);  value = Wlin[(k4*4+w4)*32 + (2*lcc+half)]
    for (int i = t; i < 4096; i += 512) {
        int w4   = i & 3;
        int lcc  = (i >> 2) & 15;
        int half = (i >> 6) & 1;
        int k4   = i >> 7;
        sW3[i] = Wlin[(k4*4 + w4)*32 + (2*lcc + half)];
    }
    if (t < 32) { sWE[t] = We[t]; sWG[t] = Wg[t]; sWEP[t] = Wep[t]; sWGP[t] = Wgp[t]; }
    __syncthreads();

    // ---- phase 1: z @ W_lin + b_lin --------------------------------------
    // lane = (h, lcc): h = lane>>4 picks row-subset, lcc = lane&15 picks cc-pair.
    // Per pass: 8 rows staged; half h computes rows 4h..4h+3 for cc {2lcc, 2lcc+1}.
    {
        const size_t rstep = (size_t)16 * NC_ * E_;     // np stride of 16
        const float* zp0 = z + (((size_t)b * NP_ + w) * NC_ + nc) * E_;
        float* myZ = sZ + w*8*128;
        int lcc = lane & 15, h = lane >> 4;
        const ulonglong2* wv3 = reinterpret_cast<const ulonglong2*>(sW3);
        float2 bl2 = *reinterpret_cast<const float2*>(blin + 2*lcc);

        for (int g = 0; g < 4; g++) {
            const float* zg = zp0 + (size_t)(8*g) * rstep;
            float4 cur[8];
#pragma unroll
            for (int r = 0; r < 8; r++)
                cur[r] = reinterpret_cast<const float4*>(zg + (size_t)r * rstep)[lane];
#pragma unroll
            for (int r = 0; r < 8; r++)
                reinterpret_cast<float4*>(myZ + r*128)[lane] = cur[r];
            __syncwarp();

            ull acc[4][2];
#pragma unroll
            for (int j = 0; j < 4; j++) { acc[j][0] = 0ull; acc[j][1] = 0ull; }

#pragma unroll
            for (int k4 = 0; k4 < 32; k4++) {
                ulonglong2 wva = wv3[(k4*2    )*16 + lcc];   // cc even half
                ulonglong2 wvb = wv3[(k4*2 + 1)*16 + lcc];   // cc odd half
#pragma unroll
                for (int j = 0; j < 4; j++) {
                    ulonglong2 v = reinterpret_cast<const ulonglong2*>(myZ + (4*h + j)*128)[k4];
                    FMA2(acc[j][0], v.x, wva.x);
                    FMA2(acc[j][0], v.y, wva.y);
                    FMA2(acc[j][1], v.x, wvb.x);
                    FMA2(acc[j][1], v.y, wvb.y);
                }
            }
#pragma unroll
            for (int j = 0; j < 4; j++) {
                float a0, a1, b0, b1;
                unpack2(a0, a1, acc[j][0]);
                unpack2(b0, b1, acc[j][1]);
                int np = w + 16 * (8*g + 4*h + j);
                *reinterpret_cast<float2*>(&sT[np*36 + 2*lcc]) =
                    make_float2((a0 + a1) + bl2.x, (b0 + b1) + bl2.y);
            }
            __syncwarp();
        }
    }
    __syncthreads();

    // ---- phase 2: softmax over np, + dis_bias, weird-reshape mask ----
    for (int cr = w; cr < 32; cr += 16) {
        float vv[16];
        float mx = -3.0e38f;
#pragma unroll
        for (int i = 0; i < 16; i++) { vv[i] = sT[(lane + 32*i)*36 + cr]; mx = fmaxf(mx, vv[i]); }
#pragma unroll
        for (int off = 16; off >= 1; off >>= 1) mx = fmaxf(mx, __shfl_xor_sync(0xffffffffu, mx, off));
        float sum = 0.f;
#pragma unroll
        for (int i = 0; i < 16; i++) { vv[i] = __expf(vv[i] - mx); sum += vv[i]; }
#pragma unroll
        for (int off = 16; off >= 1; off >>= 1) sum += __shfl_xor_sync(0xffffffffu, sum, off);
        float inv = 1.0f / sum;

        size_t gb = (size_t)b * CQ_ + (size_t)(cr * NC_ + nc) * NP_;
        size_t mb = (size_t)(cr & 3) * Q_ + (size_t)nc * NP_;
#pragma unroll
        for (int i = 0; i < 16; i++) {
            int np = lane + 32 * i;
            float val = fmaf(vv[i], inv, g_disb[gb + np]);
            if (mask_at(zmask, mb + np, mt)) val = 1e-9f;
            sT[np*36 + cr] = val;
        }
    }
    __syncthreads();

    // ---- phase 3: gated energy heads, accumulate per-b ----
    {
        float bE = be[0], bG = bg[0], bEp = bep[0], bGp = bgp[0];
        float se = 0.f, sp = 0.f;
        {
            int np = t;
            float ea = 0.f, ga = 0.f, e2 = 0.f, g2 = 0.f;
#pragma unroll
            for (int cc = 0; cc < 32; cc++) {
                float v = sT[np*36 + cc];
                ea = fmaf(v, sWE[cc],  ea);
                ga = fmaf(v, sWG[cc],  ga);
                e2 = fmaf(v, sWEP[cc], e2);
                g2 = fmaf(v, sWGP[cc], g2);
            }
            if (mask_at(zmask, ((size_t)b * NP_ + np) * NC_ + nc, mt)) {
                se = (ea + bE)  / (1.f + __expf(-(ga + bG)));
                sp = (e2 + bEp) / (1.f + __expf(-(g2 + bGp)));
            }
        }
#pragma unroll
        for (int off = 16; off >= 1; off >>= 1) {
            se += __shfl_xor_sync(0xffffffffu, se, off);
            sp += __shfl_xor_sync(0xffffffffu, sp, off);
        }
        if (lane == 0) { sRed[w] = se; sRed[16 + w] = sp; }
        __syncthreads();
        if (t == 0) {
            float a = 0.f, p2 = 0.f;
            for (int i = 0; i < 16; i++) { a += sRed[i]; p2 += sRed[16 + i]; }
            atomicAdd(&g_acc[b],     a);
            atomicAdd(&g_acc[4 + b], p2);
        }
    }

    // ---- phase 4 (fused lig): O[cc][e] = sum_np sT[np][cc] * pocket[b][np][e]
    // warp w -> e-slice [8w, 8w+8); lane: lc = lane&7 -> cc-quad 4lc..4lc+3,
    // le = lane>>3 -> e-pair e0 = 8w+2le. Thread tile: 4cc x 2e, acc as cc-pairs.
    {
        int lc = lane & 7, le = lane >> 3;
        int e0 = w*8 + le*2;
        ull acc[4] = {0ull,0ull,0ull,0ull};   // [e][ccpair]

        for (int c0 = 0; c0 < 8; c0++) {
            __syncthreads();    // previous chunk fully consumed (covers aliasing too)
            const float4* Pg = reinterpret_cast<const float4*>(
                pocket + ((size_t)b * NP_ + c0 * 64) * E_);
            float4* sP4 = reinterpret_cast<float4*>(sP);
#pragma unroll
            for (int u = 0; u < 4; u++) sP4[t + 512*u] = Pg[t + 512*u];
            __syncthreads();

            const float* sTc = sT + (c0*64)*36 + lc*4;
#pragma unroll 4
            for (int np = 0; np < 64; np++) {
                ulonglong2 a4 = *reinterpret_cast<const ulonglong2*>(sTc + np*36);
                float2 pv = *reinterpret_cast<const float2*>(&sP[np*128 + e0]);
                ull d0 = pack2(pv.x, pv.x);
                ull d1 = pack2(pv.y, pv.y);
                FMA2(acc[0], a4.x, d0);
                FMA2(acc[1], a4.y, d0);
                FMA2(acc[2], a4.x, d1);
                FMA2(acc[3], a4.y, d1);
            }
        }
#pragma unroll
        for (int cp = 0; cp < 2; cp++) {
            float x0, x1, y0, y1;
            unpack2(x0, x1, acc[cp]);       // cc 4lc+2cp, 4lc+2cp+1 @ e0
            unpack2(y0, y1, acc[2 + cp]);   // same cc @ e0+1
            int cc0 = lc*4 + 2*cp;
            *reinterpret_cast<float2*>(
                g_lig + (((size_t)b * C_ + cc0) * NC_ + nc) * E_ + e0) = make_float2(x0, y0);
            *reinterpret_cast<float2*>(
                g_lig + (((size_t)b * C_ + cc0 + 1) * NC_ + nc) * E_ + e0) = make_float2(x1, y1);
        }
    }
}

// ---------------- K5: split-K GEMM partials -------------------------------
// grid (2 eo-halves, 16 M-tiles of 64 rows, 16 K-chunks of 2 cc), 256 threads.
__global__ void __launch_bounds__(256) k_out(const float* __restrict__ Wout)
{
    extern __shared__ float smem[];
    float* sAt = smem;            // [128 e][64 r]  (A transposed)
    float* sB  = smem + 8192;     // [128 e][64 eo]

    int t   = threadIdx.x;
    int eo0 = blockIdx.x * 64;
    int y   = blockIdx.y;         // M tile: rows y*64 .. y*64+63
    int kc  = blockIdx.z;         // cc group: 2*kc .. 2*kc+1
    int b   = y >> 2;
    int nc0 = (y & 3) * 64;
    int tx  = t & 15, ty = t >> 4;

    ull acc[4][2];
#pragma unroll
    for (int i = 0; i < 4; i++) { acc[i][0] = 0ull; acc[i][1] = 0ull; }

    for (int c = 0; c < 2; c++) {
        int ccg = kc*2 + c;
        const float* Ab = g_lig + (((size_t)b * C_ + ccg) * NC_ + nc0) * E_;
        const float* Bb = Wout + ((size_t)ccg * 128) * E_ + eo0;
        __syncthreads();
#pragma unroll
        for (int p = 0; p < 8; p++) {
            int idx = p*256 + t;
            int r = idx & 63, e4 = idx >> 6;
            float4 v = reinterpret_cast<const float4*>(Ab + (size_t)r * E_)[e4];
            sAt[(4*e4+0)*64 + r] = v.x;
            sAt[(4*e4+1)*64 + r] = v.y;
            sAt[(4*e4+2)*64 + r] = v.z;
            sAt[(4*e4+3)*64 + r] = v.w;
        }
#pragma unroll
        for (int p = 0; p < 8; p++) {
            int idx = p*256 + t;
            int c4 = idx & 15, e = idx >> 4;
            reinterpret_cast<float4*>(sB + e*64)[c4] =
                reinterpret_cast<const float4*>(Bb + (size_t)e * E_)[c4];
        }
        __syncthreads();
#pragma unroll 8
        for (int e = 0; e < 128; e++) {
            float4 av = *reinterpret_cast<const float4*>(&sAt[e*64 + 4*ty]);
            ulonglong2 bv = *reinterpret_cast<const ulonglong2*>(&sB[e*64 + 4*tx]);
            ull d0 = pack2(av.x, av.x);
            FMA2(acc[0][0], d0, bv.x); FMA2(acc[0][1], d0, bv.y);
            ull d1 = pack2(av.y, av.y);
            FMA2(acc[1][0], d1, bv.x); FMA2(acc[1][1], d1, bv.y);
            ull d2 = pack2(av.z, av.z);
            FMA2(acc[2][0], d2, bv.x); FMA2(acc[2][1], d2, bv.y);
            ull d3 = pack2(av.w, av.w);
            FMA2(acc[3][0], d3, bv.x); FMA2(acc[3][1], d3, bv.y);
        }
    }
#pragma unroll
    for (int i = 0; i < 4; i++) {
        float4 o;
        unpack2(o.x, o.y, acc[i][0]);
        unpack2(o.z, o.w, acc[i][1]);
        int row = y*64 + 4*ty + i;
        *reinterpret_cast<float4*>(
            &g_part[((size_t)kc * 1024 + row) * 128 + eo0 + 4*tx]) = o;
    }
}

// ---------------- K5b: reduce split-K partials + bias ---------------------
__global__ void __launch_bounds__(256) k_red(const float* __restrict__ bout,
                                             float* __restrict__ out)
{
    int i4 = blockIdx.x * 256 + threadIdx.x;        // float4 index, < 32768
    const float4* P = reinterpret_cast<const float4*>(g_part);
    float4 s = P[i4];
#pragma unroll
    for (int k = 1; k < 16; k++) {
        float4 v = P[(size_t)k * 32768 + i4];
        s.x += v.x; s.y += v.y; s.z += v.z; s.w += v.w;
    }
    float4 bo = reinterpret_cast<const float4*>(bout)[i4 & 31];
    s.x += bo.x; s.y += bo.y; s.z += bo.z; s.w += bo.w;
    reinterpret_cast<float4*>(out)[i4] = s;
}

// ---------------- K6: finalize affinity / prmsd ---------------------------
__global__ void k_fin(const float* __restrict__ bias,
                      const float* __restrict__ bias_p,
                      float* __restrict__ out)
{
    int t = threadIdx.x;
    if (t < 4) {
        float a = bias[0] + g_acc[t];
        out[131072 + t] = (a > 0.f) ? a : 0.01f * a;
        float p = bias_p[0] + g_acc[4 + t];
        out[131076 + t] = (p > 0.f) ? p : 0.01f * p;
    }
}

// ---------------- launch --------------------------------------------------
extern "C" void kernel_launch(void* const* d_in, const int* in_sizes, int n_in,
                              void* d_out, int out_size)
{
    const float* z      = (const float*)d_in[0];
    const void*  zmask  = d_in[1];
    const float* pocket = (const float*)d_in[2];
    const float* cand   = (const float*)d_in[3];
    const float* Wlin   = (const float*)d_in[4];
    const float* blin   = (const float*)d_in[5];
    const float* Wdis   = (const float*)d_in[6];
    const float* bdis   = (const float*)d_in[7];
    const float* We     = (const float*)d_in[8];
    const float* be     = (const float*)d_in[9];
    const float* Wg     = (const float*)d_in[10];
    const float* bg     = (const float*)d_in[11];
    const float* bias   = (const float*)d_in[12];
    const float* Wep    = (const float*)d_in[13];
    const float* bep    = (const float*)d_in[14];
    const float* Wgp    = (const float*)d_in[15];
    const float* bgp    = (const float*)d_in[16];
    const float* biasp  = (const float*)d_in[17];
    const float* Wout   = (const float*)d_in[18];
    const float* bout   = (const float*)d_in[19];
    float* out = (float*)d_out;

    const int K1_SMEM = 39072 * 4;    // 156288 bytes
    const int KO_SMEM = 16384 * 4;    // 65536 bytes
    cudaFuncSetAttribute(k_main, cudaFuncAttributeMaxDynamicSharedMemorySize, K1_SMEM);
    cudaFuncSetAttribute(k_out,  cudaFuncAttributeMaxDynamicSharedMemorySize, KO_SMEM);

    // launch index:            0         1       2 (pad so k_main lands at 3)
    k_detect<<<1, 32>>>((const unsigned int*)zmask);
    k_disb<<<(B_*NP_*NC_)/8, 256>>>(cand, Wdis, bdis);
    k_detect<<<1, 32>>>((const unsigned int*)zmask);   // idempotent pad launch
    k_main<<<B_*NC_, 512, K1_SMEM>>>(z, zmask, pocket, Wlin, blin,
                                     We, be, Wg, bg, Wep, bep, Wgp, bgp);
    k_out<<<dim3(2, 16, 16), 256, KO_SMEM>>>(Wout);
    k_red<<<128, 256>>>(bout, out);
    k_fin<<<1, 32>>>(bias, biasp, out);
}

// round 13
// speedup vs baseline: 1.1994x; 1.0735x over previous
#include <cuda_runtime.h>
#include <cstdint>
#include <cstddef>

#define B_   4
#define NP_  512
#define NC_  256
#define E_   128
#define C_   32
#define Q_   (NP_*NC_)          // 131072
#define CQ_  (C_*Q_)            // 4194304 per batch
#define NB_  20

typedef unsigned long long ull;

// ---------------- f32x2 packed helpers ------------------------------------
#define FMA2(d, a, b) asm("fma.rn.f32x2 %0, %1, %2, %0;" : "+l"(d) : "l"(a), "l"(b))
#define ADD2(d, a, b) asm("add.rn.f32x2 %0, %1, %2;" : "=l"(d) : "l"(a), "l"(b))
__device__ __forceinline__ ull pack2(float x, float y) {
    ull r; asm("mov.b64 %0, {%1, %2};" : "=l"(r) : "f"(x), "f"(y)); return r;
}
__device__ __forceinline__ void unpack2(float& x, float& y, ull v) {
    asm("mov.b64 {%0, %1}, %2;" : "=f"(x), "=f"(y) : "l"(v));
}

// ---------------- scratch (device globals; no allocation) ----------------
__device__ float g_disb[(size_t)B_*NP_*NC_*C_];   // natural [b][np][nc][cc] flat
__device__ float g_lig [(size_t)B_*C_*NC_*E_];    // [b][cc][nc][e]
__device__ float g_part[(size_t)16*1024*128];     // split-K partials for k_out
__device__ float g_acc [8];                       // [0..3]=energy, [4..7]=prmsd
__device__ int   g_mtype;                         // 0=u8, 1=i32, 2=f32

// ---------------- K-1: detect z_mask dtype --------------------------------
__global__ void k_detect(const unsigned int* __restrict__ m)
{
    if (threadIdx.x == 0) {
        bool alli = true, allf = true;
        for (int i = 0; i < 64; i++) {
            unsigned int v = m[i * 97];
            if (!(v == 0u || v == 1u))           alli = false;
            if (!(v == 0u || v == 0x3F800000u))  allf = false;
        }
        g_mtype = alli ? 1 : (allf ? 2 : 0);
    }
}

__device__ __forceinline__ bool mask_at(const void* zm, size_t idx, int mt)
{
    if (mt == 1) return ((const int*)zm)[idx] != 0;
    if (mt == 2) return ((const float*)zm)[idx] != 0.f;
    return ((const unsigned char*)zm)[idx] != 0;
}

// ---------------- K0: distance-bucket bias --------------------------------
__global__ void __launch_bounds__(256) k_disb(const float* __restrict__ cand,
                                              const float* __restrict__ Wd,
                                              const float* __restrict__ bd)
{
    __shared__ float sWd[NB_*32];
    __shared__ float sBd[32];
    __shared__ float sCd[8];
    int t = threadIdx.x;
    for (int i = t; i < NB_*32; i += 256) sWd[i] = Wd[i];
    if (t < 32) sBd[t] = bd[t];
    if (t < 8)  sCd[t] = cand[blockIdx.x * 8 + t];   // one 32B sector
    __syncthreads();

    int w = t >> 5, lane = t & 31;
    int s = blockIdx.x * 8 + w;              // s = (b*NP+np)*NC+nc
    float x = sCd[w];

    float ev = 0.f;
    if (lane < NB_) {
        float v  = (float)(lane + 1) * (15.0f / 21.0f);
        float d  = (x - v) * (21.0f / 15.0f);
        float a  = d + 1.0f;
        float c2 = 1.0f - d;
        if (a > 0.f && c2 > 0.f)
            ev = 8.4335730689f * __expf(-__fdividef(1.f, a) - __fdividef(1.f, c2));
    }
    float acc = sBd[lane];
#pragma unroll
    for (int k = 0; k < NB_; k++) {
        float ek = __shfl_sync(0xffffffffu, ev, k);
        acc = fmaf(ek, sWd[k*32 + lane], acc);
    }
    g_disb[(size_t)s * 32 + lane] = acc;

    if (blockIdx.x == 0 && t < 8) g_acc[t] = 0.f;   // stream-ordered before k_main
}

// ---------------- K1: fused zlin GEMM + softmax + bias + mask + energy + lig
// 512 threads (16 warps). Dynamic smem layout (floats):
//   [0, 4096)       sW3: W_lin as 16B k-quad chunks [32 k4][2 half][16 lcc][4]
//   [4096, 36864)   sZ: 16 warps x 16 rows x 128         (phase 1)
//   [0, 8192)       sP[64][128] pocket chunk             (phase 4, aliases)
//   [8192, 12288)   sR: 16KB phase-4 np-half reduction   (phase 4, inside sZ)
//   [36864, 55296)  sT[512][36]
//   [55296, 55424)  sWE/sWG/sWEP/sWGP (4x32)
//   [55424, 55456)  sRed[32]
// Total 55456 floats = 221824 B.
__global__ void __launch_bounds__(512) k_main(const float* __restrict__ z,
                                              const void* __restrict__ zmask,
                                              const float* __restrict__ pocket,
                                              const float* __restrict__ Wlin,
                                              const float* __restrict__ blin,
                                              const float* __restrict__ We,  const float* __restrict__ be,
                                              const float* __restrict__ Wg,  const float* __restrict__ bg,
                                              const float* __restrict__ Wep, const float* __restrict__ bep,
                                              const float* __restrict__ Wgp, const float* __restrict__ bgp)
{
    extern __shared__ float smem[];
    float* sW3  = smem;                  // 4096: chunked W_lin
    float* sZ   = smem + 4096;           // 16 warps x 16 rows x 128
    float* sP   = smem;                  // phase-4 pocket chunk (aliases)
    ull*   sR   = (ull*)(smem + 8192);   // phase-4 reduction buffer (in sZ area)
    float* sT   = smem + 36864;          // [512][36]
    float* sWE  = smem + 55296;
    float* sWG  = sWE + 32;
    float* sWEP = sWG + 32;
    float* sWGP = sWEP + 32;
    float* sRed = sWGP + 32;             // [32]

    int t    = threadIdx.x;
    int b    = blockIdx.x >> 8;
    int nc   = blockIdx.x & 255;
    int w    = t >> 5, lane = t & 31;
    int mt   = g_mtype;

    // Build sW3: chunk (k4*2 + half)*16 + lcc holds W[2*lcc+half][4k4..4k4+3]
    for (int i = t; i < 4096; i += 512) {
        int w4   = i & 3;
        int lcc  = (i >> 2) & 15;
        int half = (i >> 6) & 1;
        int k4   = i >> 7;
        sW3[i] = Wlin[(k4*4 + w4)*32 + (2*lcc + half)];
    }
    if (t < 32) { sWE[t] = We[t]; sWG[t] = Wg[t]; sWEP[t] = Wep[t]; sWGP[t] = Wgp[t]; }
    __syncthreads();

    // ---- phase 1: z @ W_lin + b_lin (R=8 rows per half, 16 staged/pass) ----
    {
        const size_t rstep = (size_t)16 * NC_ * E_;     // np stride of 16
        const float* zp0 = z + (((size_t)b * NP_ + w) * NC_ + nc) * E_;
        float* myZ = sZ + w*16*128;
        int lcc = lane & 15, h = lane >> 4;
        const ulonglong2* wv3 = reinterpret_cast<const ulonglong2*>(sW3);
        float2 bl2 = *reinterpret_cast<const float2*>(blin + 2*lcc);

        for (int g = 0; g < 2; g++) {
            const float* zg = zp0 + (size_t)(16*g) * rstep;
#pragma unroll
            for (int bb = 0; bb < 2; bb++) {
                float4 cur[8];
#pragma unroll
                for (int r = 0; r < 8; r++)
                    cur[r] = reinterpret_cast<const float4*>(zg + (size_t)(bb*8 + r) * rstep)[lane];
#pragma unroll
                for (int r = 0; r < 8; r++)
                    reinterpret_cast<float4*>(myZ + (bb*8 + r)*128)[lane] = cur[r];
            }
            __syncwarp();

            ull acc[8][2];
#pragma unroll
            for (int j = 0; j < 8; j++) { acc[j][0] = 0ull; acc[j][1] = 0ull; }

#pragma unroll
            for (int k4 = 0; k4 < 32; k4++) {
                ulonglong2 wva = wv3[(k4*2    )*16 + lcc];   // cc even
                ulonglong2 wvb = wv3[(k4*2 + 1)*16 + lcc];   // cc odd
#pragma unroll
                for (int j = 0; j < 8; j++) {
                    ulonglong2 v = reinterpret_cast<const ulonglong2*>(myZ + (8*h + j)*128)[k4];
                    FMA2(acc[j][0], v.x, wva.x);
                    FMA2(acc[j][0], v.y, wva.y);
                    FMA2(acc[j][1], v.x, wvb.x);
                    FMA2(acc[j][1], v.y, wvb.y);
                }
            }
#pragma unroll
            for (int j = 0; j < 8; j++) {
                float a0, a1, b0, b1;
                unpack2(a0, a1, acc[j][0]);
                unpack2(b0, b1, acc[j][1]);
                int np = w + 16 * (16*g + 8*h + j);
                *reinterpret_cast<float2*>(&sT[np*36 + 2*lcc]) =
                    make_float2((a0 + a1) + bl2.x, (b0 + b1) + bl2.y);
            }
            __syncwarp();
        }
    }
    __syncthreads();

    // ---- phase 2: softmax over np, + dis_bias, weird-reshape mask ----
    for (int cr = w; cr < 32; cr += 16) {
        float vv[16];
        float mx = -3.0e38f;
#pragma unroll
        for (int i = 0; i < 16; i++) { vv[i] = sT[(lane + 32*i)*36 + cr]; mx = fmaxf(mx, vv[i]); }
#pragma unroll
        for (int off = 16; off >= 1; off >>= 1) mx = fmaxf(mx, __shfl_xor_sync(0xffffffffu, mx, off));
        float sum = 0.f;
#pragma unroll
        for (int i = 0; i < 16; i++) { vv[i] = __expf(vv[i] - mx); sum += vv[i]; }
#pragma unroll
        for (int off = 16; off >= 1; off >>= 1) sum += __shfl_xor_sync(0xffffffffu, sum, off);
        float inv = 1.0f / sum;

        size_t gb = (size_t)b * CQ_ + (size_t)(cr * NC_ + nc) * NP_;
        size_t mb = (size_t)(cr & 3) * Q_ + (size_t)nc * NP_;
#pragma unroll
        for (int i = 0; i < 16; i++) {
            int np = lane + 32 * i;
            float val = fmaf(vv[i], inv, g_disb[gb + np]);
            if (mask_at(zmask, mb + np, mt)) val = 1e-9f;
            sT[np*36 + cr] = val;
        }
    }
    __syncthreads();

    // ---- phase 3: gated energy heads (float4 row reads) ----
    {
        float bE = be[0], bG = bg[0], bEp = bep[0], bGp = bgp[0];
        float se = 0.f, sp = 0.f;
        {
            int np = t;
            const float4* row = reinterpret_cast<const float4*>(sT + np*36);
            float ea = 0.f, ga = 0.f, e2 = 0.f, g2 = 0.f;
#pragma unroll
            for (int i = 0; i < 8; i++) {
                float4 v = row[i];
                ea = fmaf(v.x, sWE[4*i+0], ea); ea = fmaf(v.y, sWE[4*i+1], ea);
                ea = fmaf(v.z, sWE[4*i+2], ea); ea = fmaf(v.w, sWE[4*i+3], ea);
                ga = fmaf(v.x, sWG[4*i+0], ga); ga = fmaf(v.y, sWG[4*i+1], ga);
                ga = fmaf(v.z, sWG[4*i+2], ga); ga = fmaf(v.w, sWG[4*i+3], ga);
                e2 = fmaf(v.x, sWEP[4*i+0], e2); e2 = fmaf(v.y, sWEP[4*i+1], e2);
                e2 = fmaf(v.z, sWEP[4*i+2], e2); e2 = fmaf(v.w, sWEP[4*i+3], e2);
                g2 = fmaf(v.x, sWGP[4*i+0], g2); g2 = fmaf(v.y, sWGP[4*i+1], g2);
                g2 = fmaf(v.z, sWGP[4*i+2], g2); g2 = fmaf(v.w, sWGP[4*i+3], g2);
            }
            if (mask_at(zmask, ((size_t)b * NP_ + np) * NC_ + nc, mt)) {
                se = (ea + bE)  / (1.f + __expf(-(ga + bG)));
                sp = (e2 + bEp) / (1.f + __expf(-(g2 + bGp)));
            }
        }
#pragma unroll
        for (int off = 16; off >= 1; off >>= 1) {
            se += __shfl_xor_sync(0xffffffffu, se, off);
            sp += __shfl_xor_sync(0xffffffffu, sp, off);
        }
        if (lane == 0) { sRed[w] = se; sRed[16 + w] = sp; }
        __syncthreads();
        if (t == 0) {
            float a = 0.f, p2 = 0.f;
            for (int i = 0; i < 16; i++) { a += sRed[i]; p2 += sRed[16 + i]; }
            atomicAdd(&g_acc[b],     a);
            atomicAdd(&g_acc[4 + b], p2);
        }
    }

    // ---- phase 4 (fused lig): O[cc][e] = sum_np sT[np][cc] * pocket[b][np][e]
    // warp w: es = w&7 -> e-slice [16es,16es+16), h2 = w>>3 -> np-half.
    // lane: lc = lane&7 -> cc-quad 4lc..4lc+3; le = lane>>3 -> e-quad e0 = 16es+4le.
    // Thread tile 4cc x 4e; np-halves summed via sR afterwards.
    {
        int lc = lane & 7, le = lane >> 3;
        int es = w & 7,  h2 = w >> 3;
        int e0 = es*16 + le*4;
        ull acc[2][4];                     // [ccpair][e]
#pragma unroll
        for (int i = 0; i < 4; i++) { acc[0][i] = 0ull; acc[1][i] = 0ull; }

        for (int c0 = 0; c0 < 8; c0++) {
            __syncthreads();    // previous chunk fully consumed (covers aliasing too)
            const float4* Pg = reinterpret_cast<const float4*>(
                pocket + ((size_t)b * NP_ + c0 * 64) * E_);
            float4* sP4 = reinterpret_cast<float4*>(sP);
#pragma unroll
            for (int u = 0; u < 4; u++) sP4[t + 512*u] = Pg[t + 512*u];
            __syncthreads();

            const float* sTc = sT + (c0*64 + h2*32)*36 + lc*4;
            const float* sPc = sP + h2*32*128 + e0;
#pragma unroll 4
            for (int np = 0; np < 32; np++) {
                ulonglong2 a4 = *reinterpret_cast<const ulonglong2*>(sTc + np*36);
                float4 pv = *reinterpret_cast<const float4*>(sPc + np*128);
                ull d0 = pack2(pv.x, pv.x);
                ull d1 = pack2(pv.y, pv.y);
                ull d2 = pack2(pv.z, pv.z);
                ull d3 = pack2(pv.w, pv.w);
                FMA2(acc[0][0], a4.x, d0); FMA2(acc[1][0], a4.y, d0);
                FMA2(acc[0][1], a4.x, d1); FMA2(acc[1][1], a4.y, d1);
                FMA2(acc[0][2], a4.x, d2); FMA2(acc[1][2], a4.y, d2);
                FMA2(acc[0][3], a4.x, d3); FMA2(acc[1][3], a4.y, d3);
            }
        }
        __syncthreads();                    // sP fully consumed before sR reuse-safety
        if (h2 == 0) {                      // stage np-half-0 partials
#pragma unroll
            for (int i = 0; i < 4; i++) {
                sR[(2*i    )*256 + es*32 + lane] = acc[0][i];
                sR[(2*i + 1)*256 + es*32 + lane] = acc[1][i];
            }
        }
        __syncthreads();
        if (h2 == 1) {                      // sum halves, store
#pragma unroll
            for (int i = 0; i < 4; i++) {
                ull o0, o1;
                ADD2(o0, acc[0][i], sR[(2*i    )*256 + es*32 + lane]);
                ADD2(o1, acc[1][i], sR[(2*i + 1)*256 + es*32 + lane]);
                acc[0][i] = o0; acc[1][i] = o1;
            }
#pragma unroll
            for (int cp = 0; cp < 2; cp++) {
                float4 ve, vo;
                unpack2(ve.x, vo.x, acc[cp][0]);
                unpack2(ve.y, vo.y, acc[cp][1]);
                unpack2(ve.z, vo.z, acc[cp][2]);
                unpack2(ve.w, vo.w, acc[cp][3]);
                int cc0 = lc*4 + 2*cp;
                *reinterpret_cast<float4*>(
                    g_lig + (((size_t)b * C_ + cc0) * NC_ + nc) * E_ + e0) = ve;
                *reinterpret_cast<float4*>(
                    g_lig + (((size_t)b * C_ + cc0 + 1) * NC_ + nc) * E_ + e0) = vo;
            }
        }
    }
}

// ---------------- K5: split-K GEMM partials -------------------------------
// grid (2 eo-halves, 16 M-tiles of 64 rows, 16 K-chunks of 2 cc), 256 threads.
__global__ void __launch_bounds__(256) k_out(const float* __restrict__ Wout)
{
    extern __shared__ float smem[];
    float* sAt = smem;            // [128 e][64 r]  (A transposed)
    float* sB  = smem + 8192;     // [128 e][64 eo]

    int t   = threadIdx.x;
    int eo0 = blockIdx.x * 64;
    int y   = blockIdx.y;         // M tile: rows y*64 .. y*64+63
    int kc  = blockIdx.z;         // cc group: 2*kc .. 2*kc+1
    int b   = y >> 2;
    int nc0 = (y & 3) * 64;
    int tx  = t & 15, ty = t >> 4;

    ull acc[4][2];
#pragma unroll
    for (int i = 0; i < 4; i++) { acc[i][0] = 0ull; acc[i][1] = 0ull; }

    for (int c = 0; c < 2; c++) {
        int ccg = kc*2 + c;
        const float* Ab = g_lig + (((size_t)b * C_ + ccg) * NC_ + nc0) * E_;
        const float* Bb = Wout + ((size_t)ccg * 128) * E_ + eo0;
        __syncthreads();
#pragma unroll
        for (int p = 0; p < 8; p++) {
            int idx = p*256 + t;
            int r = idx & 63, e4 = idx >> 6;
            float4 v = reinterpret_cast<const float4*>(Ab + (size_t)r * E_)[e4];
            sAt[(4*e4+0)*64 + r] = v.x;
            sAt[(4*e4+1)*64 + r] = v.y;
            sAt[(4*e4+2)*64 + r] = v.z;
            sAt[(4*e4+3)*64 + r] = v.w;
        }
#pragma unroll
        for (int p = 0; p < 8; p++) {
            int idx = p*256 + t;
            int c4 = idx & 15, e = idx >> 4;
            reinterpret_cast<float4*>(sB + e*64)[c4] =
                reinterpret_cast<const float4*>(Bb + (size_t)e * E_)[c4];
        }
        __syncthreads();
#pragma unroll 8
        for (int e = 0; e < 128; e++) {
            float4 av = *reinterpret_cast<const float4*>(&sAt[e*64 + 4*ty]);
            ulonglong2 bv = *reinterpret_cast<const ulonglong2*>(&sB[e*64 + 4*tx]);
            ull d0 = pack2(av.x, av.x);
            FMA2(acc[0][0], d0, bv.x); FMA2(acc[0][1], d0, bv.y);
            ull d1 = pack2(av.y, av.y);
            FMA2(acc[1][0], d1, bv.x); FMA2(acc[1][1], d1, bv.y);
            ull d2 = pack2(av.z, av.z);
            FMA2(acc[2][0], d2, bv.x); FMA2(acc[2][1], d2, bv.y);
            ull d3 = pack2(av.w, av.w);
            FMA2(acc[3][0], d3, bv.x); FMA2(acc[3][1], d3, bv.y);
        }
    }
#pragma unroll
    for (int i = 0; i < 4; i++) {
        float4 o;
        unpack2(o.x, o.y, acc[i][0]);
        unpack2(o.z, o.w, acc[i][1]);
        int row = y*64 + 4*ty + i;
        *reinterpret_cast<float4*>(
            &g_part[((size_t)kc * 1024 + row) * 128 + eo0 + 4*tx]) = o;
    }
}

// ---------------- K5b: reduce split-K partials + bias ---------------------
__global__ void __launch_bounds__(256) k_red(const float* __restrict__ bout,
                                             float* __restrict__ out)
{
    int i4 = blockIdx.x * 256 + threadIdx.x;        // float4 index, < 32768
    const float4* P = reinterpret_cast<const float4*>(g_part);
    float4 s = P[i4];
#pragma unroll
    for (int k = 1; k < 16; k++) {
        float4 v = P[(size_t)k * 32768 + i4];
        s.x += v.x; s.y += v.y; s.z += v.z; s.w += v.w;
    }
    float4 bo = reinterpret_cast<const float4*>(bout)[i4 & 31];
    s.x += bo.x; s.y += bo.y; s.z += bo.z; s.w += bo.w;
    reinterpret_cast<float4*>(out)[i4] = s;
}

// ---------------- K6: finalize affinity / prmsd ---------------------------
__global__ void k_fin(const float* __restrict__ bias,
                      const float* __restrict__ bias_p,
                      float* __restrict__ out)
{
    int t = threadIdx.x;
    if (t < 4) {
        float a = bias[0] + g_acc[t];
        out[131072 + t] = (a > 0.f) ? a : 0.01f * a;
        float p = bias_p[0] + g_acc[4 + t];
        out[131076 + t] = (p > 0.f) ? p : 0.01f * p;
    }
}

// ---------------- launch --------------------------------------------------
extern "C" void kernel_launch(void* const* d_in, const int* in_sizes, int n_in,
                              void* d_out, int out_size)
{
    const float* z      = (const float*)d_in[0];
    const void*  zmask  = d_in[1];
    const float* pocket = (const float*)d_in[2];
    const float* cand   = (const float*)d_in[3];
    const float* Wlin   = (const float*)d_in[4];
    const float* blin   = (const float*)d_in[5];
    const float* Wdis   = (const float*)d_in[6];
    const float* bdis   = (const float*)d_in[7];
    const float* We     = (const float*)d_in[8];
    const float* be     = (const float*)d_in[9];
    const float* Wg     = (const float*)d_in[10];
    const float* bg     = (const float*)d_in[11];
    const float* bias   = (const float*)d_in[12];
    const float* Wep    = (const float*)d_in[13];
    const float* bep    = (const float*)d_in[14];
    const float* Wgp    = (const float*)d_in[15];
    const float* bgp    = (const float*)d_in[16];
    const float* biasp  = (const float*)d_in[17];
    const float* Wout   = (const float*)d_in[18];
    const float* bout   = (const float*)d_in[19];
    float* out = (float*)d_out;

    const int K1_SMEM = 55456 * 4;    // 221824 bytes
    const int KO_SMEM = 16384 * 4;    // 65536 bytes
    cudaFuncSetAttribute(k_main, cudaFuncAttributeMaxDynamicSharedMemorySize, K1_SMEM);
    cudaFuncSetAttribute(k_out,  cudaFuncAttributeMaxDynamicSharedMemorySize, KO_SMEM);

    // launch index:            0         1       2 (pad so k_main lands at 3)
    k_detect<<<1, 32>>>((const unsigned int*)zmask);
    k_disb<<<(B_*NP_*NC_)/8, 256>>>(cand, Wdis, bdis);
    k_detect<<<1, 32>>>((const unsigned int*)zmask);   // idempotent pad launch
    k_main<<<B_*NC_, 512, K1_SMEM>>>(z, zmask, pocket, Wlin, blin,
                                     We, be, Wg, bg, Wep, bep, Wgp, bgp);
    k_out<<<dim3(2, 16, 16), 256, KO_SMEM>>>(Wout);
    k_red<<<128, 256>>>(bout, out);
    k_fin<<<1, 32>>>(bias, biasp, out);
}

// round 14
// speedup vs baseline: 1.3370x; 1.1148x over previous
#include <cuda_runtime.h>
#include <cstdint>
#include <cstddef>

#define B_   4
#define NP_  512
#define NC_  256
#define E_   128
#define C_   32
#define Q_   (NP_*NC_)          // 131072
#define CQ_  (C_*Q_)            // 4194304 per batch
#define NB_  20

typedef unsigned long long ull;

// ---------------- f32x2 packed helpers ------------------------------------
#define FMA2(d, a, b) asm("fma.rn.f32x2 %0, %1, %2, %0;" : "+l"(d) : "l"(a), "l"(b))
#define ADD2(d, a, b) asm("add.rn.f32x2 %0, %1, %2;" : "=l"(d) : "l"(a), "l"(b))
__device__ __forceinline__ ull pack2(float x, float y) {
    ull r; asm("mov.b64 %0, {%1, %2};" : "=l"(r) : "f"(x), "f"(y)); return r;
}
__device__ __forceinline__ void unpack2(float& x, float& y, ull v) {
    asm("mov.b64 {%0, %1}, %2;" : "=f"(x), "=f"(y) : "l"(v));
}

// ---------------- scratch (device globals; no allocation) ----------------
__device__ float g_lig [(size_t)B_*C_*NC_*E_];    // [b][cc][nc][e]
__device__ float g_part[(size_t)16*1024*128];     // split-K partials for k_out
__device__ float g_acc [8];                       // [0..3]=energy, [4..7]=prmsd
__device__ int   g_mtype;                         // 0=u8, 1=i32, 2=f32

// ---------------- K-1: detect z_mask dtype + zero accumulators ------------
__global__ void k_detect(const unsigned int* __restrict__ m)
{
    int t = threadIdx.x;
    if (t < 8) g_acc[t] = 0.f;
    if (t == 0) {
        bool alli = true, allf = true;
        for (int i = 0; i < 64; i++) {
            unsigned int v = m[i * 97];
            if (!(v == 0u || v == 1u))           alli = false;
            if (!(v == 0u || v == 0x3F800000u))  allf = false;
        }
        g_mtype = alli ? 1 : (allf ? 2 : 0);
    }
}

__device__ __forceinline__ bool mask_at(const void* zm, size_t idx, int mt)
{
    if (mt == 1) return ((const int*)zm)[idx] != 0;
    if (mt == 2) return ((const float*)zm)[idx] != 0.f;
    return ((const unsigned char*)zm)[idx] != 0;
}

// ---------------- K1: fused zlin GEMM + softmax + disb + mask + energy + lig
// 512 threads (16 warps). Dynamic smem layout (floats):
//   [0, 4096)       sW3: W_lin as 16B k-quad chunks [32 k4][2 half][16 lcc][4]
//   [4096, 36864)   sZ: 16 warps x 16 rows x 128         (phase 1)
//   [0, 8192)       sP[64][128] pocket chunk             (phase 4, aliases)
//   [8192, 12288)   sR: phase-4 np-half reduction        (phase 4, inside sZ)
//   [12288, 24576)  sEmb[512 sid][24] edge embeddings    (phase 2, inside sZ)
//   [36864, 55296)  sT[512][36]
//   [55296, 55424)  sWE/sWG/sWEP/sWGP (4x32)
//   [55424, 55456)  sRed[32]
// Total 55456 floats = 221824 B.
__global__ void __launch_bounds__(512) k_main(const float* __restrict__ z,
                                              const void* __restrict__ zmask,
                                              const float* __restrict__ pocket,
                                              const float* __restrict__ cand,
                                              const float* __restrict__ Wlin,
                                              const float* __restrict__ blin,
                                              const float* __restrict__ Wdis,
                                              const float* __restrict__ bdis,
                                              const float* __restrict__ We,  const float* __restrict__ be,
                                              const float* __restrict__ Wg,  const float* __restrict__ bg,
                                              const float* __restrict__ Wep, const float* __restrict__ bep,
                                              const float* __restrict__ Wgp, const float* __restrict__ bgp)
{
    extern __shared__ float smem[];
    float* sW3  = smem;                  // 4096: chunked W_lin
    float* sZ   = smem + 4096;           // 16 warps x 16 rows x 128
    float* sP   = smem;                  // phase-4 pocket chunk (aliases)
    ull*   sR   = (ull*)(smem + 8192);   // phase-4 reduction buffer (in sZ area)
    float* sEmb = smem + 12288;          // [512][24] embeddings (in sZ area)
    float* sT   = smem + 36864;          // [512][36]
    float* sWE  = smem + 55296;
    float* sWG  = sWE + 32;
    float* sWEP = sWG + 32;
    float* sWGP = sWEP + 32;
    float* sRed = sWGP + 32;             // [32]

    int t    = threadIdx.x;
    int b    = blockIdx.x >> 8;
    int nc   = blockIdx.x & 255;
    int w    = t >> 5, lane = t & 31;
    int mt   = g_mtype;

    // Build sW3: chunk (k4*2 + half)*16 + lcc holds W[2*lcc+half][4k4..4k4+3]
    for (int i = t; i < 4096; i += 512) {
        int w4   = i & 3;
        int lcc  = (i >> 2) & 15;
        int half = (i >> 6) & 1;
        int k4   = i >> 7;
        sW3[i] = Wlin[(k4*4 + w4)*32 + (2*lcc + half)];
    }
    if (t < 32) { sWE[t] = We[t]; sWG[t] = Wg[t]; sWEP[t] = Wep[t]; sWGP[t] = Wgp[t]; }
    __syncthreads();

    // ---- phase 1: z @ W_lin + b_lin (R=8 rows per half, 16 staged/pass) ----
    {
        const size_t rstep = (size_t)16 * NC_ * E_;     // np stride of 16
        const float* zp0 = z + (((size_t)b * NP_ + w) * NC_ + nc) * E_;
        float* myZ = sZ + w*16*128;
        int lcc = lane & 15, h = lane >> 4;
        const ulonglong2* wv3 = reinterpret_cast<const ulonglong2*>(sW3);
        float2 bl2 = *reinterpret_cast<const float2*>(blin + 2*lcc);

        for (int g = 0; g < 2; g++) {
            const float* zg = zp0 + (size_t)(16*g) * rstep;
#pragma unroll
            for (int bb = 0; bb < 2; bb++) {
                float4 cur[8];
#pragma unroll
                for (int r = 0; r < 8; r++)
                    cur[r] = reinterpret_cast<const float4*>(zg + (size_t)(bb*8 + r) * rstep)[lane];
#pragma unroll
                for (int r = 0; r < 8; r++)
                    reinterpret_cast<float4*>(myZ + (bb*8 + r)*128)[lane] = cur[r];
            }
            __syncwarp();

            ull acc[8][2];
#pragma unroll
            for (int j = 0; j < 8; j++) { acc[j][0] = 0ull; acc[j][1] = 0ull; }

#pragma unroll
            for (int k4 = 0; k4 < 32; k4++) {
                ulonglong2 wva = wv3[(k4*2    )*16 + lcc];   // cc even
                ulonglong2 wvb = wv3[(k4*2 + 1)*16 + lcc];   // cc odd
#pragma unroll
                for (int j = 0; j < 8; j++) {
                    ulonglong2 v = reinterpret_cast<const ulonglong2*>(myZ + (8*h + j)*128)[k4];
                    FMA2(acc[j][0], v.x, wva.x);
                    FMA2(acc[j][0], v.y, wva.y);
                    FMA2(acc[j][1], v.x, wvb.x);
                    FMA2(acc[j][1], v.y, wvb.y);
                }
            }
#pragma unroll
            for (int j = 0; j < 8; j++) {
                float a0, a1, b0, b1;
                unpack2(a0, a1, acc[j][0]);
                unpack2(b0, b1, acc[j][1]);
                int np = w + 16 * (16*g + 8*h + j);
                *reinterpret_cast<float2*>(&sT[np*36 + 2*lcc]) =
                    make_float2((a0 + a1) + bl2.x, (b0 + b1) + bl2.y);
            }
            __syncwarp();
        }
    }
    __syncthreads();

    // ---- phase 2a: stage edge embeddings for this block's dis_bias slice ----
    // sid = cr*16 + i needs cand[b, cr*16 + (nc>>4), (nc&15)*16 + i].
    // Thread t = sid computes its scalar's 20 smooth_finite buckets.
    {
        int hb = nc >> 4, lb = nc & 15;
        int cr_s = t >> 4, i_s = t & 15;
        float x = cand[((size_t)b * NP_ + cr_s*16 + hb) * NC_ + lb*16 + i_s];
        float e[20];
#pragma unroll
        for (int k = 0; k < NB_; k++) {
            float v  = (float)(k + 1) * (15.0f / 21.0f);
            float d  = (x - v) * (21.0f / 15.0f);
            float a  = d + 1.0f;
            float c2 = 1.0f - d;
            e[k] = (a > 0.f && c2 > 0.f)
                 ? 8.4335730689f * __expf(-__fdividef(1.f, a) - __fdividef(1.f, c2))
                 : 0.f;
        }
        float4* dst = reinterpret_cast<float4*>(sEmb + t*24);
        dst[0] = make_float4(e[0],  e[1],  e[2],  e[3]);
        dst[1] = make_float4(e[4],  e[5],  e[6],  e[7]);
        dst[2] = make_float4(e[8],  e[9],  e[10], e[11]);
        dst[3] = make_float4(e[12], e[13], e[14], e[15]);
        dst[4] = make_float4(e[16], e[17], e[18], e[19]);
    }
    __syncthreads();

    // ---- phase 2b: softmax over np, + computed dis_bias, mask ----
    {
        float wd[20];
#pragma unroll
        for (int k = 0; k < NB_; k++) wd[k] = Wdis[k*32 + lane];
        float bdl = bdis[lane];

        for (int cr = w; cr < 32; cr += 16) {
            float vv[16];
            float mx = -3.0e38f;
#pragma unroll
            for (int i = 0; i < 16; i++) { vv[i] = sT[(lane + 32*i)*36 + cr]; mx = fmaxf(mx, vv[i]); }
#pragma unroll
            for (int off = 16; off >= 1; off >>= 1) mx = fmaxf(mx, __shfl_xor_sync(0xffffffffu, mx, off));
            float sum = 0.f;
#pragma unroll
            for (int i = 0; i < 16; i++) { vv[i] = __expf(vv[i] - mx); sum += vv[i]; }
#pragma unroll
            for (int off = 16; off >= 1; off >>= 1) sum += __shfl_xor_sync(0xffffffffu, sum, off);
            float inv = 1.0f / sum;

            size_t mb = (size_t)(cr & 3) * Q_ + (size_t)nc * NP_;
#pragma unroll
            for (int i = 0; i < 16; i++) {
                const float4* em = reinterpret_cast<const float4*>(sEmb + (cr*16 + i)*24);
                float4 e0 = em[0], e1 = em[1], e2 = em[2], e3 = em[3], e4 = em[4];
                float disb = bdl;
                disb = fmaf(e0.x, wd[0],  disb); disb = fmaf(e0.y, wd[1],  disb);
                disb = fmaf(e0.z, wd[2],  disb); disb = fmaf(e0.w, wd[3],  disb);
                disb = fmaf(e1.x, wd[4],  disb); disb = fmaf(e1.y, wd[5],  disb);
                disb = fmaf(e1.z, wd[6],  disb); disb = fmaf(e1.w, wd[7],  disb);
                disb = fmaf(e2.x, wd[8],  disb); disb = fmaf(e2.y, wd[9],  disb);
                disb = fmaf(e2.z, wd[10], disb); disb = fmaf(e2.w, wd[11], disb);
                disb = fmaf(e3.x, wd[12], disb); disb = fmaf(e3.y, wd[13], disb);
                disb = fmaf(e3.z, wd[14], disb); disb = fmaf(e3.w, wd[15], disb);
                disb = fmaf(e4.x, wd[16], disb); disb = fmaf(e4.y, wd[17], disb);
                disb = fmaf(e4.z, wd[18], disb); disb = fmaf(e4.w, wd[19], disb);

                int np = lane + 32 * i;
                float val = fmaf(vv[i], inv, disb);
                if (mask_at(zmask, mb + np, mt)) val = 1e-9f;
                sT[np*36 + cr] = val;
            }
        }
    }
    __syncthreads();

    // ---- phase 3: gated energy heads (float4 row reads) ----
    {
        float bE = be[0], bG = bg[0], bEp = bep[0], bGp = bgp[0];
        float se = 0.f, sp = 0.f;
        {
            int np = t;
            const float4* row = reinterpret_cast<const float4*>(sT + np*36);
            float ea = 0.f, ga = 0.f, e2 = 0.f, g2 = 0.f;
#pragma unroll
            for (int i = 0; i < 8; i++) {
                float4 v = row[i];
                ea = fmaf(v.x, sWE[4*i+0], ea); ea = fmaf(v.y, sWE[4*i+1], ea);
                ea = fmaf(v.z, sWE[4*i+2], ea); ea = fmaf(v.w, sWE[4*i+3], ea);
                ga = fmaf(v.x, sWG[4*i+0], ga); ga = fmaf(v.y, sWG[4*i+1], ga);
                ga = fmaf(v.z, sWG[4*i+2], ga); ga = fmaf(v.w, sWG[4*i+3], ga);
                e2 = fmaf(v.x, sWEP[4*i+0], e2); e2 = fmaf(v.y, sWEP[4*i+1], e2);
                e2 = fmaf(v.z, sWEP[4*i+2], e2); e2 = fmaf(v.w, sWEP[4*i+3], e2);
                g2 = fmaf(v.x, sWGP[4*i+0], g2); g2 = fmaf(v.y, sWGP[4*i+1], g2);
                g2 = fmaf(v.z, sWGP[4*i+2], g2); g2 = fmaf(v.w, sWGP[4*i+3], g2);
            }
            if (mask_at(zmask, ((size_t)b * NP_ + np) * NC_ + nc, mt)) {
                se = (ea + bE)  / (1.f + __expf(-(ga + bG)));
                sp = (e2 + bEp) / (1.f + __expf(-(g2 + bGp)));
            }
        }
#pragma unroll
        for (int off = 16; off >= 1; off >>= 1) {
            se += __shfl_xor_sync(0xffffffffu, se, off);
            sp += __shfl_xor_sync(0xffffffffu, sp, off);
        }
        if (lane == 0) { sRed[w] = se; sRed[16 + w] = sp; }
        __syncthreads();
        if (t == 0) {
            float a = 0.f, p2 = 0.f;
            for (int i = 0; i < 16; i++) { a += sRed[i]; p2 += sRed[16 + i]; }
            atomicAdd(&g_acc[b],     a);
            atomicAdd(&g_acc[4 + b], p2);
        }
    }

    // ---- phase 4 (fused lig): O[cc][e] = sum_np sT[np][cc] * pocket[b][np][e]
    // warp w: es = w&7 -> e-slice [16es,16es+16), h2 = w>>3 -> np-half.
    // lane: lc = lane&7 -> cc-quad 4lc..4lc+3; le = lane>>3 -> e-quad e0 = 16es+4le.
    {
        int lc = lane & 7, le = lane >> 3;
        int es = w & 7,  h2 = w >> 3;
        int e0 = es*16 + le*4;
        ull acc[2][4];                     // [ccpair][e]
#pragma unroll
        for (int i = 0; i < 4; i++) { acc[0][i] = 0ull; acc[1][i] = 0ull; }

        for (int c0 = 0; c0 < 8; c0++) {
            __syncthreads();    // previous chunk fully consumed (covers aliasing too)
            const float4* Pg = reinterpret_cast<const float4*>(
                pocket + ((size_t)b * NP_ + c0 * 64) * E_);
            float4* sP4 = reinterpret_cast<float4*>(sP);
#pragma unroll
            for (int u = 0; u < 4; u++) sP4[t + 512*u] = Pg[t + 512*u];
            __syncthreads();

            const float* sTc = sT + (c0*64 + h2*32)*36 + lc*4;
            const float* sPc = sP + h2*32*128 + e0;
#pragma unroll 4
            for (int np = 0; np < 32; np++) {
                ulonglong2 a4 = *reinterpret_cast<const ulonglong2*>(sTc + np*36);
                float4 pv = *reinterpret_cast<const float4*>(sPc + np*128);
                ull d0 = pack2(pv.x, pv.x);
                ull d1 = pack2(pv.y, pv.y);
                ull d2 = pack2(pv.z, pv.z);
                ull d3 = pack2(pv.w, pv.w);
                FMA2(acc[0][0], a4.x, d0); FMA2(acc[1][0], a4.y, d0);
                FMA2(acc[0][1], a4.x, d1); FMA2(acc[1][1], a4.y, d1);
                FMA2(acc[0][2], a4.x, d2); FMA2(acc[1][2], a4.y, d2);
                FMA2(acc[0][3], a4.x, d3); FMA2(acc[1][3], a4.y, d3);
            }
        }
        __syncthreads();                    // sP fully consumed before sR reuse
        if (h2 == 0) {                      // stage np-half-0 partials
#pragma unroll
            for (int i = 0; i < 4; i++) {
                sR[(2*i    )*256 + es*32 + lane] = acc[0][i];
                sR[(2*i + 1)*256 + es*32 + lane] = acc[1][i];
            }
        }
        __syncthreads();
        if (h2 == 1) {                      // sum halves, store
#pragma unroll
            for (int i = 0; i < 4; i++) {
                ull o0, o1;
                ADD2(o0, acc[0][i], sR[(2*i    )*256 + es*32 + lane]);
                ADD2(o1, acc[1][i], sR[(2*i + 1)*256 + es*32 + lane]);
                acc[0][i] = o0; acc[1][i] = o1;
            }
#pragma unroll
            for (int cp = 0; cp < 2; cp++) {
                float4 ve, vo;
                unpack2(ve.x, vo.x, acc[cp][0]);
                unpack2(ve.y, vo.y, acc[cp][1]);
                unpack2(ve.z, vo.z, acc[cp][2]);
                unpack2(ve.w, vo.w, acc[cp][3]);
                int cc0 = lc*4 + 2*cp;
                *reinterpret_cast<float4*>(
                    g_lig + (((size_t)b * C_ + cc0) * NC_ + nc) * E_ + e0) = ve;
                *reinterpret_cast<float4*>(
                    g_lig + (((size_t)b * C_ + cc0 + 1) * NC_ + nc) * E_ + e0) = vo;
            }
        }
    }
}

// ---------------- K5: split-K GEMM partials -------------------------------
// grid (2 eo-halves, 16 M-tiles of 64 rows, 16 K-chunks of 2 cc), 256 threads.
__global__ void __launch_bounds__(256) k_out(const float* __restrict__ Wout)
{
    extern __shared__ float smem[];
    float* sAt = smem;            // [128 e][64 r]  (A transposed)
    float* sB  = smem + 8192;     // [128 e][64 eo]

    int t   = threadIdx.x;
    int eo0 = blockIdx.x * 64;
    int y   = blockIdx.y;         // M tile: rows y*64 .. y*64+63
    int kc  = blockIdx.z;         // cc group: 2*kc .. 2*kc+1
    int b   = y >> 2;
    int nc0 = (y & 3) * 64;
    int tx  = t & 15, ty = t >> 4;

    ull acc[4][2];
#pragma unroll
    for (int i = 0; i < 4; i++) { acc[i][0] = 0ull; acc[i][1] = 0ull; }

    for (int c = 0; c < 2; c++) {
        int ccg = kc*2 + c;
        const float* Ab = g_lig + (((size_t)b * C_ + ccg) * NC_ + nc0) * E_;
        const float* Bb = Wout + ((size_t)ccg * 128) * E_ + eo0;
        __syncthreads();
#pragma unroll
        for (int p = 0; p < 8; p++) {
            int idx = p*256 + t;
            int r = idx & 63, e4 = idx >> 6;
            float4 v = reinterpret_cast<const float4*>(Ab + (size_t)r * E_)[e4];
            sAt[(4*e4+0)*64 + r] = v.x;
            sAt[(4*e4+1)*64 + r] = v.y;
            sAt[(4*e4+2)*64 + r] = v.z;
            sAt[(4*e4+3)*64 + r] = v.w;
        }
#pragma unroll
        for (int p = 0; p < 8; p++) {
            int idx = p*256 + t;
            int c4 = idx & 15, e = idx >> 4;
            reinterpret_cast<float4*>(sB + e*64)[c4] =
                reinterpret_cast<const float4*>(Bb + (size_t)e * E_)[c4];
        }
        __syncthreads();
#pragma unroll 8
        for (int e = 0; e < 128; e++) {
            float4 av = *reinterpret_cast<const float4*>(&sAt[e*64 + 4*ty]);
            ulonglong2 bv = *reinterpret_cast<const ulonglong2*>(&sB[e*64 + 4*tx]);
            ull d0 = pack2(av.x, av.x);
            FMA2(acc[0][0], d0, bv.x); FMA2(acc[0][1], d0, bv.y);
            ull d1 = pack2(av.y, av.y);
            FMA2(acc[1][0], d1, bv.x); FMA2(acc[1][1], d1, bv.y);
            ull d2 = pack2(av.z, av.z);
            FMA2(acc[2][0], d2, bv.x); FMA2(acc[2][1], d2, bv.y);
            ull d3 = pack2(av.w, av.w);
            FMA2(acc[3][0], d3, bv.x); FMA2(acc[3][1], d3, bv.y);
        }
    }
#pragma unroll
    for (int i = 0; i < 4; i++) {
        float4 o;
        unpack2(o.x, o.y, acc[i][0]);
        unpack2(o.z, o.w, acc[i][1]);
        int row = y*64 + 4*ty + i;
        *reinterpret_cast<float4*>(
            &g_part[((size_t)kc * 1024 + row) * 128 + eo0 + 4*tx]) = o;
    }
}

// ---------------- K5b: reduce split-K partials + bias ---------------------
__global__ void __launch_bounds__(256) k_red(const float* __restrict__ bout,
                                             float* __restrict__ out)
{
    int i4 = blockIdx.x * 256 + threadIdx.x;        // float4 index, < 32768
    const float4* P = reinterpret_cast<const float4*>(g_part);
    float4 s = P[i4];
#pragma unroll
    for (int k = 1; k < 16; k++) {
        float4 v = P[(size_t)k * 32768 + i4];
        s.x += v.x; s.y += v.y; s.z += v.z; s.w += v.w;
    }
    float4 bo = reinterpret_cast<const float4*>(bout)[i4 & 31];
    s.x += bo.x; s.y += bo.y; s.z += bo.z; s.w += bo.w;
    reinterpret_cast<float4*>(out)[i4] = s;
}

// ---------------- K6: finalize affinity / prmsd ---------------------------
__global__ void k_fin(const float* __restrict__ bias,
                      const float* __restrict__ bias_p,
                      float* __restrict__ out)
{
    int t = threadIdx.x;
    if (t < 4) {
        float a = bias[0] + g_acc[t];
        out[131072 + t] = (a > 0.f) ? a : 0.01f * a;
        float p = bias_p[0] + g_acc[4 + t];
        out[131076 + t] = (p > 0.f) ? p : 0.01f * p;
    }
}

// ---------------- launch --------------------------------------------------
extern "C" void kernel_launch(void* const* d_in, const int* in_sizes, int n_in,
                              void* d_out, int out_size)
{
    const float* z      = (const float*)d_in[0];
    const void*  zmask  = d_in[1];
    const float* pocket = (const float*)d_in[2];
    const float* cand   = (const float*)d_in[3];
    const float* Wlin   = (const float*)d_in[4];
    const float* blin   = (const float*)d_in[5];
    const float* Wdis   = (const float*)d_in[6];
    const float* bdis   = (const float*)d_in[7];
    const float* We     = (const float*)d_in[8];
    const float* be     = (const float*)d_in[9];
    const float* Wg     = (const float*)d_in[10];
    const float* bg     = (const float*)d_in[11];
    const float* bias   = (const float*)d_in[12];
    const float* Wep    = (const float*)d_in[13];
    const float* bep    = (const float*)d_in[14];
    const float* Wgp    = (const float*)d_in[15];
    const float* bgp    = (const float*)d_in[16];
    const float* biasp  = (const float*)d_in[17];
    const float* Wout   = (const float*)d_in[18];
    const float* bout   = (const float*)d_in[19];
    float* out = (float*)d_out;

    const int K1_SMEM = 55456 * 4;    // 221824 bytes
    const int KO_SMEM = 16384 * 4;    // 65536 bytes
    cudaFuncSetAttribute(k_main, cudaFuncAttributeMaxDynamicSharedMemorySize, K1_SMEM);
    cudaFuncSetAttribute(k_out,  cudaFuncAttributeMaxDynamicSharedMemorySize, KO_SMEM);

    // pads keep k_main at profile launch index 3 (k_detect is idempotent)
    k_detect<<<1, 32>>>((const unsigned int*)zmask);
    k_detect<<<1, 32>>>((const unsigned int*)zmask);
    k_detect<<<1, 32>>>((const unsigned int*)zmask);
    k_main<<<B_*NC_, 512, K1_SMEM>>>(z, zmask, pocket, cand, Wlin, blin, Wdis, bdis,
                                     We, be, Wg, bg, Wep, bep, Wgp, bgp);
    k_out<<<dim3(2, 16, 16), 256, KO_SMEM>>>(Wout);
    k_red<<<128, 256>>>(bout, out);
    k_fin<<<1, 32>>>(bias, biasp, out);
}

// round 16
// speedup vs baseline: 1.4217x; 1.0634x over previous
#include <cuda_runtime.h>
#include <cstdint>
#include <cstddef>

#define B_   4
#define NP_  512
#define NC_  256
#define E_   128
#define C_   32
#define Q_   (NP_*NC_)          // 131072
#define CQ_  (C_*Q_)            // 4194304 per batch
#define NB_  20

typedef unsigned long long ull;

// ---------------- f32x2 packed helpers ------------------------------------
#define FMA2(d, a, b) asm("fma.rn.f32x2 %0, %1, %2, %0;" : "+l"(d) : "l"(a), "l"(b))
#define ADD2(d, a, b) asm("add.rn.f32x2 %0, %1, %2;" : "=l"(d) : "l"(a), "l"(b))
__device__ __forceinline__ ull pack2(float x, float y) {
    ull r; asm("mov.b64 %0, {%1, %2};" : "=l"(r) : "f"(x), "f"(y)); return r;
}
__device__ __forceinline__ void unpack2(float& x, float& y, ull v) {
    asm("mov.b64 {%0, %1}, %2;" : "=f"(x), "=f"(y) : "l"(v));
}

// ---------------- scratch (device globals; no allocation) ----------------
__device__ float g_lig [(size_t)B_*C_*NC_*E_];    // [b][cc][nc][e]
__device__ float g_part[(size_t)16*1024*128];     // split-K partials for k_out
__device__ float g_acc [8];                       // [0..3]=energy, [4..7]=prmsd
__device__ int   g_mtype;                         // 0=u8, 1=i32, 2=f32

// ---------------- K-1: detect z_mask dtype + zero accumulators ------------
__global__ void k_detect(const unsigned int* __restrict__ m)
{
    int t = threadIdx.x;
    if (t < 8) g_acc[t] = 0.f;
    if (t == 0) {
        bool alli = true, allf = true;
        for (int i = 0; i < 64; i++) {
            unsigned int v = m[i * 97];
            if (!(v == 0u || v == 1u))           alli = false;
            if (!(v == 0u || v == 0x3F800000u))  allf = false;
        }
        g_mtype = alli ? 1 : (allf ? 2 : 0);
    }
}

__device__ __forceinline__ bool mask_at(const void* zm, size_t idx, int mt)
{
    if (mt == 1) return ((const int*)zm)[idx] != 0;
    if (mt == 2) return ((const float*)zm)[idx] != 0.f;
    return ((const unsigned char*)zm)[idx] != 0;
}

// ---------------- K1: fused zlin GEMM + softmax + disb + mask + energy + lig
// 512 threads (16 warps). Dynamic smem layout (floats):
//   [0, 4096)       sW3: W_lin as 16B k-quad chunks [32 k4][2 half][16 lcc][4]
//   [4096, 36864)   sZ: 16 warps x 16 rows x 128         (phase 1)
//   [0, 8192)       sP[64][128] pocket chunk             (phase 4, aliases)
//   [8192, 12288)   sR: phase-4 np-half reduction        (phase 4, inside sZ)
//   [12288, 14336)  sEmb[512 sid][4] sparse embeddings   (phase 2, inside sZ)
//   [36864, 55296)  sT[512][36]
//   [55296, 55424)  sWE/sWG/sWEP/sWGP (4x32)
//   [55424, 55456)  sRed[32]
//   [55456, 56096)  sWd[20][32]
// Total 56096 floats = 224384 B.
__global__ void __launch_bounds__(512) k_main(const float* __restrict__ z,
                                              const void* __restrict__ zmask,
                                              const float* __restrict__ pocket,
                                              const float* __restrict__ cand,
                                              const float* __restrict__ Wlin,
                                              const float* __restrict__ blin,
                                              const float* __restrict__ Wdis,
                                              const float* __restrict__ bdis,
                                              const float* __restrict__ We,  const float* __restrict__ be,
                                              const float* __restrict__ Wg,  const float* __restrict__ bg,
                                              const float* __restrict__ Wep, const float* __restrict__ bep,
                                              const float* __restrict__ Wgp, const float* __restrict__ bgp)
{
    extern __shared__ float smem[];
    float* sW3  = smem;                  // 4096: chunked W_lin
    float* sZ   = smem + 4096;           // 16 warps x 16 rows x 128
    float* sP   = smem;                  // phase-4 pocket chunk (aliases)
    ull*   sR   = (ull*)(smem + 8192);   // phase-4 reduction buffer (in sZ area)
    float* sEmb = smem + 12288;          // [512][4] sparse embeddings (in sZ area)
    float* sT   = smem + 36864;          // [512][36]
    float* sWE  = smem + 55296;
    float* sWG  = sWE + 32;
    float* sWEP = sWG + 32;
    float* sWGP = sWEP + 32;
    float* sRed = sWGP + 32;             // [32]
    float* sWd  = smem + 55456;          // [20][32]

    int t    = threadIdx.x;
    int b    = blockIdx.x >> 8;
    int nc   = blockIdx.x & 255;
    int w    = t >> 5, lane = t & 31;
    int mt   = g_mtype;

    // Build sW3: chunk (k4*2 + half)*16 + lcc holds W[2*lcc+half][4k4..4k4+3]
    for (int i = t; i < 4096; i += 512) {
        int w4   = i & 3;
        int lcc  = (i >> 2) & 15;
        int half = (i >> 6) & 1;
        int k4   = i >> 7;
        sW3[i] = Wlin[(k4*4 + w4)*32 + (2*lcc + half)];
    }
    if (t < 32) { sWE[t] = We[t]; sWG[t] = Wg[t]; sWEP[t] = Wep[t]; sWGP[t] = Wgp[t]; }
    if (t < 640 && t >= 512) sWd[t - 512 + 512] = Wdis[t - 512 + 512];   // covered below anyway
    for (int i = t; i < 640; i += 512) sWd[i] = Wdis[i];
    __syncthreads();

    // ---- phase 1: z @ W_lin + b_lin (R=8 rows per half, 16 staged/pass) ----
    {
        const size_t rstep = (size_t)16 * NC_ * E_;     // np stride of 16
        const float* zp0 = z + (((size_t)b * NP_ + w) * NC_ + nc) * E_;
        float* myZ = sZ + w*16*128;
        int lcc = lane & 15, h = lane >> 4;
        const ulonglong2* wv3 = reinterpret_cast<const ulonglong2*>(sW3);
        float2 bl2 = *reinterpret_cast<const float2*>(blin + 2*lcc);

        for (int g = 0; g < 2; g++) {
            const float* zg = zp0 + (size_t)(16*g) * rstep;
#pragma unroll
            for (int bb = 0; bb < 2; bb++) {
                float4 cur[8];
#pragma unroll
                for (int r = 0; r < 8; r++)
                    cur[r] = reinterpret_cast<const float4*>(zg + (size_t)(bb*8 + r) * rstep)[lane];
#pragma unroll
                for (int r = 0; r < 8; r++)
                    reinterpret_cast<float4*>(myZ + (bb*8 + r)*128)[lane] = cur[r];
            }
            __syncwarp();

            ull acc[8][2];
#pragma unroll
            for (int j = 0; j < 8; j++) { acc[j][0] = 0ull; acc[j][1] = 0ull; }

#pragma unroll
            for (int k4 = 0; k4 < 32; k4++) {
                ulonglong2 wva = wv3[(k4*2    )*16 + lcc];   // cc even
                ulonglong2 wvb = wv3[(k4*2 + 1)*16 + lcc];   // cc odd
#pragma unroll
                for (int j = 0; j < 8; j++) {
                    ulonglong2 v = reinterpret_cast<const ulonglong2*>(myZ + (8*h + j)*128)[k4];
                    FMA2(acc[j][0], v.x, wva.x);
                    FMA2(acc[j][0], v.y, wva.y);
                    FMA2(acc[j][1], v.x, wvb.x);
                    FMA2(acc[j][1], v.y, wvb.y);
                }
            }
#pragma unroll
            for (int j = 0; j < 8; j++) {
                float a0, a1, b0, b1;
                unpack2(a0, a1, acc[j][0]);
                unpack2(b0, b1, acc[j][1]);
                int np = w + 16 * (16*g + 8*h + j);
                *reinterpret_cast<float2*>(&sT[np*36 + 2*lcc]) =
                    make_float2((a0 + a1) + bl2.x, (b0 + b1) + bl2.y);
            }
            __syncwarp();
        }
    }
    __syncthreads();

    // ---- phase 2a: sparse edge embeddings (<=2 active buckets per scalar) ----
    // sid = cr*16 + i needs cand[b, cr*16 + (nc>>4), (nc&15)*16 + i].
    // Buckets are 1.0 apart in normalized units with support |d|<1, so only
    // k0 = clamp(ceil(u)-2, 0, 18) and k0+1 can be nonzero.
    {
        int hb = nc >> 4, lb = nc & 15;
        int cr_s = t >> 4, i_s = t & 15;
        float x = cand[((size_t)b * NP_ + cr_s*16 + hb) * NC_ + lb*16 + i_s];
        float u = x * (21.0f / 15.0f);
        int k0 = (int)ceilf(u) - 2;
        if (k0 < 0)  k0 = 0;
        if (k0 > 18) k0 = 18;
        float e0 = 0.f, e1 = 0.f;
        float d0 = u - (float)(k0 + 1);
        if (fabsf(d0) < 1.f)
            e0 = 8.4335730689f * __expf(-__fdividef(1.f, 1.f + d0) - __fdividef(1.f, 1.f - d0));
        float d1 = d0 - 1.0f;
        if (fabsf(d1) < 1.f)
            e1 = 8.4335730689f * __expf(-__fdividef(1.f, 1.f + d1) - __fdividef(1.f, 1.f - d1));
        reinterpret_cast<float4*>(sEmb)[t] =
            make_float4(e0, e1, __int_as_float(k0 * 32), 0.f);
    }
    __syncthreads();

    // ---- phase 2b: softmax over np, + sparse dis_bias, mask ----
    {
        float bdl = bdis[lane];

        for (int cr = w; cr < 32; cr += 16) {
            float vv[16];
            float mx = -3.0e38f;
#pragma unroll
            for (int i = 0; i < 16; i++) { vv[i] = sT[(lane + 32*i)*36 + cr]; mx = fmaxf(mx, vv[i]); }
#pragma unroll
            for (int off = 16; off >= 1; off >>= 1) mx = fmaxf(mx, __shfl_xor_sync(0xffffffffu, mx, off));
            float sum = 0.f;
#pragma unroll
            for (int i = 0; i < 16; i++) { vv[i] = __expf(vv[i] - mx); sum += vv[i]; }
#pragma unroll
            for (int off = 16; off >= 1; off >>= 1) sum += __shfl_xor_sync(0xffffffffu, sum, off);
            float inv = 1.0f / sum;

            size_t mb = (size_t)(cr & 3) * Q_ + (size_t)nc * NP_;
#pragma unroll
            for (int i = 0; i < 16; i++) {
                float4 em = reinterpret_cast<const float4*>(sEmb)[cr*16 + i];
                int off = __float_as_int(em.z);
                float disb = fmaf(em.x, sWd[off + lane],
                             fmaf(em.y, sWd[off + 32 + lane], bdl));

                int np = lane + 32 * i;
                float val = fmaf(vv[i], inv, disb);
                if (mask_at(zmask, mb + np, mt)) val = 1e-9f;
                sT[np*36 + cr] = val;
            }
        }
    }
    __syncthreads();

    // ---- phase 3: gated energy heads (float4 row reads) ----
    {
        float bE = be[0], bG = bg[0], bEp = bep[0], bGp = bgp[0];
        float se = 0.f, sp = 0.f;
        {
            int np = t;
            const float4* row = reinterpret_cast<const float4*>(sT + np*36);
            float ea = 0.f, ga = 0.f, e2 = 0.f, g2 = 0.f;
#pragma unroll
            for (int i = 0; i < 8; i++) {
                float4 v = row[i];
                ea = fmaf(v.x, sWE[4*i+0], ea); ea = fmaf(v.y, sWE[4*i+1], ea);
                ea = fmaf(v.z, sWE[4*i+2], ea); ea = fmaf(v.w, sWE[4*i+3], ea);
                ga = fmaf(v.x, sWG[4*i+0], ga); ga = fmaf(v.y, sWG[4*i+1], ga);
                ga = fmaf(v.z, sWG[4*i+2], ga); ga = fmaf(v.w, sWG[4*i+3], ga);
                e2 = fmaf(v.x, sWEP[4*i+0], e2); e2 = fmaf(v.y, sWEP[4*i+1], e2);
                e2 = fmaf(v.z, sWEP[4*i+2], e2); e2 = fmaf(v.w, sWEP[4*i+3], e2);
                g2 = fmaf(v.x, sWGP[4*i+0], g2); g2 = fmaf(v.y, sWGP[4*i+1], g2);
                g2 = fmaf(v.z, sWGP[4*i+2], g2); g2 = fmaf(v.w, sWGP[4*i+3], g2);
            }
            if (mask_at(zmask, ((size_t)b * NP_ + np) * NC_ + nc, mt)) {
                se = (ea + bE)  / (1.f + __expf(-(ga + bG)));
                sp = (e2 + bEp) / (1.f + __expf(-(g2 + bGp)));
            }
        }
#pragma unroll
        for (int off = 16; off >= 1; off >>= 1) {
            se += __shfl_xor_sync(0xffffffffu, se, off);
            sp += __shfl_xor_sync(0xffffffffu, sp, off);
        }
        if (lane == 0) { sRed[w] = se; sRed[16 + w] = sp; }
        __syncthreads();
        if (t == 0) {
            float a = 0.f, p2 = 0.f;
            for (int i = 0; i < 16; i++) { a += sRed[i]; p2 += sRed[16 + i]; }
            atomicAdd(&g_acc[b],     a);
            atomicAdd(&g_acc[4 + b], p2);
        }
    }

    // ---- phase 4 (fused lig): O[cc][e] = sum_np sT[np][cc] * pocket[b][np][e]
    // warp w: es = w&7 -> e-slice [16es,16es+16), h2 = w>>3 -> np-half.
    // lane: lc = lane&7 -> cc-quad 4lc..4lc+3; le = lane>>3 -> e-quad e0 = 16es+4le.
    {
        int lc = lane & 7, le = lane >> 3;
        int es = w & 7,  h2 = w >> 3;
        int e0 = es*16 + le*4;
        ull acc[2][4];                     // [ccpair][e]
#pragma unroll
        for (int i = 0; i < 4; i++) { acc[0][i] = 0ull; acc[1][i] = 0ull; }

        for (int c0 = 0; c0 < 8; c0++) {
            __syncthreads();    // previous chunk fully consumed (covers aliasing too)
            const float4* Pg = reinterpret_cast<const float4*>(
                pocket + ((size_t)b * NP_ + c0 * 64) * E_);
            float4* sP4 = reinterpret_cast<float4*>(sP);
#pragma unroll
            for (int u = 0; u < 4; u++) sP4[t + 512*u] = Pg[t + 512*u];
            __syncthreads();

            const float* sTc = sT + (c0*64 + h2*32)*36 + lc*4;
            const float* sPc = sP + h2*32*128 + e0;
#pragma unroll 4
            for (int np = 0; np < 32; np++) {
                ulonglong2 a4 = *reinterpret_cast<const ulonglong2*>(sTc + np*36);
                float4 pv = *reinterpret_cast<const float4*>(sPc + np*128);
                ull d0 = pack2(pv.x, pv.x);
                ull d1 = pack2(pv.y, pv.y);
                ull d2 = pack2(pv.z, pv.z);
                ull d3 = pack2(pv.w, pv.w);
                FMA2(acc[0][0], a4.x, d0); FMA2(acc[1][0], a4.y, d0);
                FMA2(acc[0][1], a4.x, d1); FMA2(acc[1][1], a4.y, d1);
                FMA2(acc[0][2], a4.x, d2); FMA2(acc[1][2], a4.y, d2);
                FMA2(acc[0][3], a4.x, d3); FMA2(acc[1][3], a4.y, d3);
            }
        }
        __syncthreads();                    // sP fully consumed before sR reuse
        if (h2 == 0) {                      // stage np-half-0 partials
#pragma unroll
            for (int i = 0; i < 4; i++) {
                sR[(2*i    )*256 + es*32 + lane] = acc[0][i];
                sR[(2*i + 1)*256 + es*32 + lane] = acc[1][i];
            }
        }
        __syncthreads();
        if (h2 == 1) {                      // sum halves, store
#pragma unroll
            for (int i = 0; i < 4; i++) {
                ull o0, o1;
                ADD2(o0, acc[0][i], sR[(2*i    )*256 + es*32 + lane]);
                ADD2(o1, acc[1][i], sR[(2*i + 1)*256 + es*32 + lane]);
                acc[0][i] = o0; acc[1][i] = o1;
            }
#pragma unroll
            for (int cp = 0; cp < 2; cp++) {
                float4 ve, vo;
                unpack2(ve.x, vo.x, acc[cp][0]);
                unpack2(ve.y, vo.y, acc[cp][1]);
                unpack2(ve.z, vo.z, acc[cp][2]);
                unpack2(ve.w, vo.w, acc[cp][3]);
                int cc0 = lc*4 + 2*cp;
                *reinterpret_cast<float4*>(
                    g_lig + (((size_t)b * C_ + cc0) * NC_ + nc) * E_ + e0) = ve;
                *reinterpret_cast<float4*>(
                    g_lig + (((size_t)b * C_ + cc0 + 1) * NC_ + nc) * E_ + e0) = vo;
            }
        }
    }
}

// ---------------- K5: split-K GEMM partials -------------------------------
// grid (2 eo-halves, 16 M-tiles of 64 rows, 16 K-chunks of 2 cc), 256 threads.
__global__ void __launch_bounds__(256) k_out(const float* __restrict__ Wout)
{
    extern __shared__ float smem[];
    float* sAt = smem;            // [128 e][64 r]  (A transposed)
    float* sB  = smem + 8192;     // [128 e][64 eo]

    int t   = threadIdx.x;
    int eo0 = blockIdx.x * 64;
    int y   = blockIdx.y;         // M tile: rows y*64 .. y*64+63
    int kc  = blockIdx.z;         // cc group: 2*kc .. 2*kc+1
    int b   = y >> 2;
    int nc0 = (y & 3) * 64;
    int tx  = t & 15, ty = t >> 4;

    ull acc[4][2];
#pragma unroll
    for (int i = 0; i < 4; i++) { acc[i][0] = 0ull; acc[i][1] = 0ull; }

    for (int c = 0; c < 2; c++) {
        int ccg = kc*2 + c;
        const float* Ab = g_lig + (((size_t)b * C_ + ccg) * NC_ + nc0) * E_;
        const float* Bb = Wout + ((size_t)ccg * 128) * E_ + eo0;
        __syncthreads();
#pragma unroll
        for (int p = 0; p < 8; p++) {
            int idx = p*256 + t;
            int r = idx & 63, e4 = idx >> 6;
            float4 v = reinterpret_cast<const float4*>(Ab + (size_t)r * E_)[e4];
            sAt[(4*e4+0)*64 + r] = v.x;
            sAt[(4*e4+1)*64 + r] = v.y;
            sAt[(4*e4+2)*64 + r] = v.z;
            sAt[(4*e4+3)*64 + r] = v.w;
        }
#pragma unroll
        for (int p = 0; p < 8; p++) {
            int idx = p*256 + t;
            int c4 = idx & 15, e = idx >> 4;
            reinterpret_cast<float4*>(sB + e*64)[c4] =
                reinterpret_cast<const float4*>(Bb + (size_t)e * E_)[c4];
        }
        __syncthreads();
#pragma unroll 8
        for (int e = 0; e < 128; e++) {
            float4 av = *reinterpret_cast<const float4*>(&sAt[e*64 + 4*ty]);
            ulonglong2 bv = *reinterpret_cast<const ulonglong2*>(&sB[e*64 + 4*tx]);
            ull d0 = pack2(av.x, av.x);
            FMA2(acc[0][0], d0, bv.x); FMA2(acc[0][1], d0, bv.y);
            ull d1 = pack2(av.y, av.y);
            FMA2(acc[1][0], d1, bv.x); FMA2(acc[1][1], d1, bv.y);
            ull d2 = pack2(av.z, av.z);
            FMA2(acc[2][0], d2, bv.x); FMA2(acc[2][1], d2, bv.y);
            ull d3 = pack2(av.w, av.w);
            FMA2(acc[3][0], d3, bv.x); FMA2(acc[3][1], d3, bv.y);
        }
    }
#pragma unroll
    for (int i = 0; i < 4; i++) {
        float4 o;
        unpack2(o.x, o.y, acc[i][0]);
        unpack2(o.z, o.w, acc[i][1]);
        int row = y*64 + 4*ty + i;
        *reinterpret_cast<float4*>(
            &g_part[((size_t)kc * 1024 + row) * 128 + eo0 + 4*tx]) = o;
    }
}

// ---------------- K5b: reduce split-K partials + bias ---------------------
__global__ void __launch_bounds__(256) k_red(const float* __restrict__ bout,
                                             float* __restrict__ out)
{
    int i4 = blockIdx.x * 256 + threadIdx.x;        // float4 index, < 32768
    const float4* P = reinterpret_cast<const float4*>(g_part);
    float4 s = P[i4];
#pragma unroll
    for (int k = 1; k < 16; k++) {
        float4 v = P[(size_t)k * 32768 + i4];
        s.x += v.x; s.y += v.y; s.z += v.z; s.w += v.w;
    }
    float4 bo = reinterpret_cast<const float4*>(bout)[i4 & 31];
    s.x += bo.x; s.y += bo.y; s.z += bo.z; s.w += bo.w;
    reinterpret_cast<float4*>(out)[i4] = s;
}

// ---------------- K6: finalize affinity / prmsd ---------------------------
__global__ void k_fin(const float* __restrict__ bias,
                      const float* __restrict__ bias_p,
                      float* __restrict__ out)
{
    int t = threadIdx.x;
    if (t < 4) {
        float a = bias[0] + g_acc[t];
        out[131072 + t] = (a > 0.f) ? a : 0.01f * a;
        float p = bias_p[0] + g_acc[4 + t];
        out[131076 + t] = (p > 0.f) ? p : 0.01f * p;
    }
}

// ---------------- launch --------------------------------------------------
extern "C" void kernel_launch(void* const* d_in, const int* in_sizes, int n_in,
                              void* d_out, int out_size)
{
    const float* z      = (const float*)d_in[0];
    const void*  zmask  = d_in[1];
    const float* pocket = (const float*)d_in[2];
    const float* cand   = (const float*)d_in[3];
    const float* Wlin   = (const float*)d_in[4];
    const float* blin   = (const float*)d_in[5];
    const float* Wdis   = (const float*)d_in[6];
    const float* bdis   = (const float*)d_in[7];
    const float* We     = (const float*)d_in[8];
    const float* be     = (const float*)d_in[9];
    const float* Wg     = (const float*)d_in[10];
    const float* bg     = (const float*)d_in[11];
    const float* bias   = (const float*)d_in[12];
    const float* Wep    = (const float*)d_in[13];
    const float* bep    = (const float*)d_in[14];
    const float* Wgp    = (const float*)d_in[15];
    const float* bgp    = (const float*)d_in[16];
    const float* biasp  = (const float*)d_in[17];
    const float* Wout   = (const float*)d_in[18];
    const float* bout   = (const float*)d_in[19];
    float* out = (float*)d_out;

    const int K1_SMEM = 56096 * 4;    // 224384 bytes
    const int KO_SMEM = 16384 * 4;    // 65536 bytes
    cudaFuncSetAttribute(k_main, cudaFuncAttributeMaxDynamicSharedMemorySize, K1_SMEM);
    cudaFuncSetAttribute(k_out,  cudaFuncAttributeMaxDynamicSharedMemorySize, KO_SMEM);

    // pads keep k_main at profile launch index 3 (k_detect is idempotent)
    k_detect<<<1, 32>>>((const unsigned int*)zmask);
    k_detect<<<1, 32>>>((const unsigned int*)zmask);
    k_detect<<<1, 32>>>((const unsigned int*)zmask);
    k_main<<<B_*NC_, 512, K1_SMEM>>>(z, zmask, pocket, cand, Wlin, blin, Wdis, bdis,
                                     We, be, Wg, bg, Wep, bep, Wgp, bgp);
    k_out<<<dim3(2, 16, 16), 256, KO_SMEM>>>(Wout);
    k_red<<<128, 256>>>(bout, out);
    k_fin<<<1, 32>>>(bias, biasp, out);
}